// round 8
// baseline (speedup 1.0000x reference)
#include <cuda_runtime.h>
#include <cstdint>
#include <math.h>

// Problem constants
#define BSZ   4
#define TLEN  2048
#define CDIM  1024
#define NHEAD 16
#define HDIM  64
#define MTOT  (BSZ * TLEN)          // 8192

// ---------------------------------------------------------------------------
// Scratch (device globals — no allocation allowed)
// ---------------------------------------------------------------------------
__device__ float g_q[BSZ * NHEAD * TLEN * HDIM];   // [b,h,t,d]
__device__ float g_k[BSZ * NHEAD * TLEN * HDIM];
__device__ float g_v[BSZ * NHEAD * TLEN * HDIM];
__device__ float g_att[BSZ * TLEN * CDIM];         // [b,t,c]
__device__ float g_wT[4 * CDIM * CDIM];            // W_attn^T then W_proj^T

#define WT_PROJ_OFF (3 * CDIM * CDIM)

// ---------------------------------------------------------------------------
// Portable PTX helpers (sm_80+ only; harness targets plain sm_100)
// ---------------------------------------------------------------------------
__device__ __forceinline__ uint32_t smem_u32(const void* p) {
    uint32_t a;
    asm("{ .reg .u64 t; cvta.to.shared.u64 t, %1; cvt.u32.u64 %0, t; }" : "=r"(a) : "l"(p));
    return a;
}

#define CP_ASYNC16(dst, src) \
    asm volatile("cp.async.cg.shared.global [%0], [%1], 16;" :: "r"(dst), "l"(src))
#define CP_COMMIT() asm volatile("cp.async.commit_group;")
#define CP_WAIT(n)  asm volatile("cp.async.wait_group %0;" :: "n"(n))

__device__ __forceinline__ uint32_t swz(uint32_t off) { return off ^ ((off >> 3) & 0x70); }

__device__ __forceinline__ uint32_t f2tf32(float f) {
    uint32_t r;
    asm("cvt.rna.tf32.f32 %0, %1;" : "=r"(r) : "f"(f));
    return r;
}

// split a float into tf32 hi + tf32 lo (packed)
__device__ __forceinline__ uint2 split_tf32(float f) {
    uint2 r;
    r.x = f2tf32(f);
    r.y = f2tf32(f - __uint_as_float(r.x));
    return r;
}

// m16n8k8 tf32 mma, fp32 accumulate (sm_80+)
__device__ __forceinline__ void mma_tf32(float c[4],
                                         uint32_t a0, uint32_t a1, uint32_t a2, uint32_t a3,
                                         uint32_t b0, uint32_t b1) {
    asm volatile(
        "mma.sync.aligned.m16n8k8.row.col.f32.tf32.tf32.f32 "
        "{%0,%1,%2,%3}, {%4,%5,%6,%7}, {%8,%9}, {%0,%1,%2,%3};"
        : "+f"(c[0]), "+f"(c[1]), "+f"(c[2]), "+f"(c[3])
        : "r"(a0), "r"(a1), "r"(a2), "r"(a3), "r"(b0), "r"(b1));
}

// ---------------------------------------------------------------------------
// Weight transpose: out[c][r] = in[r][c], written into g_wT + dst_off
// ---------------------------------------------------------------------------
__global__ __launch_bounds__(256)
void transpose_k(const float* __restrict__ in, int dst_off, int R, int C)
{
    __shared__ float t[32][33];
    const int c0 = blockIdx.x * 32, r0 = blockIdx.y * 32;
    const int tx = threadIdx.x, ty = threadIdx.y;
#pragma unroll
    for (int i = ty; i < 32; i += 8)
        t[i][tx] = in[(r0 + i) * C + c0 + tx];
    __syncthreads();
#pragma unroll
    for (int i = ty; i < 32; i += 8)
        g_wT[dst_off + (c0 + i) * R + r0 + tx] = t[tx][i];
}

// ---------------------------------------------------------------------------
// tf32 mma.sync GEMM (unchanged from R4/R7, passing)
// ---------------------------------------------------------------------------
#define TK          32
#define STAGES      3
#define STAGE_BYTES 32768
#define STAGE_F     8192
#define SMEM_GEMM   (STAGES * STAGE_BYTES)

template <int MODE>
__device__ __forceinline__ void load_stage(const float* Ap, const float* Bt,
                                           uint32_t sb, int m0, int n0, int tid,
                                           int s, int k0)
{
    const uint32_t base = sb + s * STAGE_BYTES;
#pragma unroll
    for (int j = 0; j < 4; j++) {
        const int idx = tid + j * 256;
        const int r = idx >> 3, c = idx & 7;
        CP_ASYNC16(base + swz(r * 128 + c * 16), Ap + (m0 + r) * CDIM + k0 + c * 4);
    }
#pragma unroll
    for (int j = 0; j < 4; j++) {
        const int idx = tid + j * 256;
        const int r = idx >> 3, c = idx & 7;
        CP_ASYNC16(base + 16384 + swz(r * 128 + c * 16), Bt + (n0 + r) * CDIM + k0 + c * 4);
    }
}

template <int MODE>
__global__ __launch_bounds__(256, 2)
void tc_gemm(const float* __restrict__ A,
             int bt_off,
             const float* __restrict__ bias,
             const float* __restrict__ bQ,
             const float* __restrict__ bK,
             const float* __restrict__ bV,
             float* __restrict__ Cout)
{
    extern __shared__ float smemf[];
    const uint32_t sb = smem_u32(smemf);
    const int tid  = threadIdx.x;
    const int lane = tid & 31;
    const int wid  = tid >> 5;
    const int gid  = lane >> 2;
    const int tig  = lane & 3;
    const int wm   = (wid & 3) * 32;
    const int wn   = (wid >> 2) * 64;

    const int m0 = blockIdx.y * 128;
    const int n0 = blockIdx.x * 128;

    const float* Ap = (MODE == 1) ? (const float*)g_att : A;
    const float* Bt = g_wT + bt_off;

    float acc[2][8][4];
#pragma unroll
    for (int mt = 0; mt < 2; mt++)
#pragma unroll
        for (int nt = 0; nt < 8; nt++)
#pragma unroll
            for (int j = 0; j < 4; j++) acc[mt][nt][j] = 0.0f;

    load_stage<MODE>(Ap, Bt, sb, m0, n0, tid, 0, 0);
    CP_COMMIT();
    load_stage<MODE>(Ap, Bt, sb, m0, n0, tid, 1, TK);
    CP_COMMIT();

    const int NIT = CDIM / TK;
    const int xr  = gid << 2;

    int slot = 0;
    for (int i = 0; i < NIT; i++) {
        CP_WAIT(1);
        __syncthreads();

        if (i + 2 < NIT)
            load_stage<MODE>(Ap, Bt, sb, m0, n0, tid, (i + 2) % STAGES, (i + 2) * TK);
        CP_COMMIT();

        const float* As = smemf + slot * STAGE_F;
        const float* Bs = As + 4096;

#pragma unroll
        for (int ks = 0; ks < 4; ks++) {
            const int c0 = ((ks * 8) + tig) ^ xr;
            const int c4 = c0 ^ 4;

            uint32_t a[2][4];
#pragma unroll
            for (int mt = 0; mt < 2; mt++) {
                const int r0 = wm + mt * 16 + gid;
                const int r1 = r0 + 8;
                a[mt][0] = f2tf32(As[r0 * 32 + c0]);
                a[mt][1] = f2tf32(As[r1 * 32 + c0]);
                a[mt][2] = f2tf32(As[r0 * 32 + c4]);
                a[mt][3] = f2tf32(As[r1 * 32 + c4]);
            }
#pragma unroll
            for (int nt = 0; nt < 8; nt++) {
                const int n = wn + nt * 8 + gid;
                const uint32_t b0 = f2tf32(Bs[n * 32 + c0]);
                const uint32_t b1 = f2tf32(Bs[n * 32 + c4]);
                mma_tf32(acc[0][nt], a[0][0], a[0][1], a[0][2], a[0][3], b0, b1);
                mma_tf32(acc[1][nt], a[1][0], a[1][1], a[1][2], a[1][3], b0, b1);
            }
        }
        slot = (slot + 1) % STAGES;
    }

#pragma unroll
    for (int mt = 0; mt < 2; mt++) {
#pragma unroll
        for (int half = 0; half < 2; half++) {
            const int row = m0 + wm + mt * 16 + gid + half * 8;
#pragma unroll
            for (int nt = 0; nt < 8; nt++) {
                const int col = n0 + wn + nt * 8 + tig * 2;
                float v0 = acc[mt][nt][half * 2 + 0] + bias[col];
                float v1 = acc[mt][nt][half * 2 + 1] + bias[col + 1];

                if (MODE == 1) {
                    *(float2*)&Cout[(size_t)row * CDIM + col] = make_float2(v0, v1);
                } else {
                    const int sec = col >> 10;
                    const int n2  = col & 1023;
                    const float* hb = (sec == 0) ? bQ : (sec == 1) ? bK : bV;
                    v0 += hb[n2];
                    v1 += hb[n2 + 1];
                    const int h  = n2 >> 6, dd = n2 & 63;
                    const int b_ = row >> 11, t = row & (TLEN - 1);
                    float* base = (sec == 0) ? g_q : (sec == 1) ? g_k : g_v;
                    *(float2*)&base[(((size_t)(b_ * NHEAD + h) * TLEN) + t) * HDIM + dd] =
                        make_float2(v0, v1);
                }
            }
        }
    }
}

// ---------------------------------------------------------------------------
// Flash attention v2: split-tf32 with PRECOMPUTED hi/lo in SMEM (packed uint2).
// 128 q-rows/CTA, 8 warps x 16 rows; K/V tiles of 64 keys.
// Inner loops are pure LDS.64 + mma (no cvt/sub). Stride 68 uint2 everywhere:
//   A/K patterns hit 8B-banks at (4*gid+tig) mod 16  -> exactly 2-way (optimal)
//   V pattern hits (4*tig+gid) mod 16                -> exactly 2-way (optimal)
// ---------------------------------------------------------------------------
#define QR     128                  // q rows per CTA
#define SQ     68                   // row stride in uint2
#define OFF_K  (QR * SQ)            // 8704
#define OFF_V  (OFF_K + 64 * SQ)    // 13056
#define OFF_P  (OFF_V + 64 * SQ)    // 17408
#define FL_SMEM ((OFF_P + QR * SQ) * 8)   // 208896 bytes

__global__ __launch_bounds__(256, 1)
void flash_mma()
{
    extern __shared__ uint2 shl[];
    uint2* Qh = shl;            // [128][68] hi/lo packed
    uint2* Kh = shl + OFF_K;    // [64][68]
    uint2* Vh = shl + OFF_V;    // [64][68]  (Vh[key][dim])
    uint2* Ph = shl + OFF_P;    // [128][68]

    const int tid  = threadIdx.x;
    const int lane = tid & 31;
    const int wid  = tid >> 5;          // 0..7
    const int gid  = lane >> 2;
    const int tig  = lane & 3;
    const int wr0  = wid * 16;

    const int qt = (int)gridDim.x - 1 - (int)blockIdx.x;   // heavy tiles first
    const int h  = blockIdx.y;
    const int b  = blockIdx.z;
    const int bh = b * NHEAD + h;
    const int q0 = qt * QR;

    // Load + convert Q once (pre-scaled by 1/sqrt(d) = 0.125)
    for (int idx = tid; idx < QR * 16; idx += 256) {
        const int row = idx >> 4, c = (idx & 15) * 4;
        float4 v = *(const float4*)(g_q + ((size_t)bh * TLEN + q0 + row) * HDIM + c);
        uint2* dst = Qh + row * SQ + c;
        dst[0] = split_tf32(v.x * 0.125f);
        dst[1] = split_tf32(v.y * 0.125f);
        dst[2] = split_tf32(v.z * 0.125f);
        dst[3] = split_tf32(v.w * 0.125f);
    }

    float o[8][4];
#pragma unroll
    for (int nt = 0; nt < 8; nt++)
#pragma unroll
        for (int j = 0; j < 4; j++) o[nt][j] = 0.0f;
    float mrow[2] = {-1e30f, -1e30f};
    float lrow[2] = {0.0f, 0.0f};

    const uint2* qa0 = Qh + (wr0 + gid) * SQ;
    const uint2* qa1 = Qh + (wr0 + gid + 8) * SQ;
    const uint2* pa0 = Ph + (wr0 + gid) * SQ;
    const uint2* pa1 = Ph + (wr0 + gid + 8) * SQ;

    const int ktmax = 2 * qt + 1;
    for (int kt = 0; kt <= ktmax; kt++) {
        __syncthreads();   // previous iteration done with Kh/Vh
        for (int idx = tid; idx < 64 * 16; idx += 256) {
            const int row = idx >> 4, c = (idx & 15) * 4;
            const size_t src = ((size_t)bh * TLEN + kt * 64 + row) * HDIM + c;
            float4 kv = *(const float4*)(g_k + src);
            float4 vv = *(const float4*)(g_v + src);
            uint2* kd = Kh + row * SQ + c;
            kd[0] = split_tf32(kv.x); kd[1] = split_tf32(kv.y);
            kd[2] = split_tf32(kv.z); kd[3] = split_tf32(kv.w);
            uint2* vd = Vh + row * SQ + c;
            vd[0] = split_tf32(vv.x); vd[1] = split_tf32(vv.y);
            vd[2] = split_tf32(vv.z); vd[3] = split_tf32(vv.w);
        }
        __syncthreads();

        // ---- S = Q K^T ----
        float s[8][4];
#pragma unroll
        for (int nt = 0; nt < 8; nt++)
#pragma unroll
            for (int j = 0; j < 4; j++) s[nt][j] = 0.0f;

#pragma unroll 2
        for (int ks = 0; ks < 8; ks++) {
            const int kc = ks * 8 + tig;
            const uint2 A0 = qa0[kc],     A1 = qa1[kc];
            const uint2 A2 = qa0[kc + 4], A3 = qa1[kc + 4];
#pragma unroll
            for (int nt = 0; nt < 8; nt++) {
                const uint2 B0 = Kh[(nt * 8 + gid) * SQ + kc];
                const uint2 B1 = Kh[(nt * 8 + gid) * SQ + kc + 4];
                mma_tf32(s[nt], A0.x, A1.x, A2.x, A3.x, B0.x, B1.x);
                mma_tf32(s[nt], A0.x, A1.x, A2.x, A3.x, B0.y, B1.y);
                mma_tf32(s[nt], A0.y, A1.y, A2.y, A3.y, B0.x, B1.x);
            }
        }

        // Causal mask (only the last two key tiles can cross the diagonal)
        if (kt >= ktmax - 1) {
            const int colb = kt * 64;
#pragma unroll
            for (int nt = 0; nt < 8; nt++) {
#pragma unroll
                for (int j = 0; j < 4; j++) {
                    const int col = colb + nt * 8 + 2 * tig + (j & 1);
                    const int row = q0 + wr0 + gid + (j >> 1) * 8;
                    if (col > row) s[nt][j] = -1e30f;
                }
            }
        }

        // Row max (quad reduction over tig)
        float tmax[2] = {-1e30f, -1e30f};
#pragma unroll
        for (int nt = 0; nt < 8; nt++) {
            tmax[0] = fmaxf(tmax[0], fmaxf(s[nt][0], s[nt][1]));
            tmax[1] = fmaxf(tmax[1], fmaxf(s[nt][2], s[nt][3]));
        }
#pragma unroll
        for (int d = 1; d <= 2; d <<= 1) {
            tmax[0] = fmaxf(tmax[0], __shfl_xor_sync(0xFFFFFFFFu, tmax[0], d));
            tmax[1] = fmaxf(tmax[1], __shfl_xor_sync(0xFFFFFFFFu, tmax[1], d));
        }
        const float mnew0 = fmaxf(mrow[0], tmax[0]);
        const float mnew1 = fmaxf(mrow[1], tmax[1]);
        const float corr0 = __expf(mrow[0] - mnew0);
        const float corr1 = __expf(mrow[1] - mnew1);

        // p = exp(s - m); split hi/lo; stage into Ph (uint4 = 2 packed cols)
        float ps[2] = {0.0f, 0.0f};
#pragma unroll
        for (int nt = 0; nt < 8; nt++) {
            const float p0 = __expf(s[nt][0] - mnew0);
            const float p1 = __expf(s[nt][1] - mnew0);
            const float p2 = __expf(s[nt][2] - mnew1);
            const float p3 = __expf(s[nt][3] - mnew1);
            ps[0] += p0 + p1;
            ps[1] += p2 + p3;
            const uint2 h0 = split_tf32(p0), h1 = split_tf32(p1);
            const uint2 h2 = split_tf32(p2), h3 = split_tf32(p3);
            *(uint4*)(pa0 + nt * 8 + 2 * tig) = make_uint4(h0.x, h0.y, h1.x, h1.y);
            *(uint4*)(pa1 + nt * 8 + 2 * tig) = make_uint4(h2.x, h2.y, h3.x, h3.y);
        }
#pragma unroll
        for (int d = 1; d <= 2; d <<= 1) {
            ps[0] += __shfl_xor_sync(0xFFFFFFFFu, ps[0], d);
            ps[1] += __shfl_xor_sync(0xFFFFFFFFu, ps[1], d);
        }
        lrow[0] = lrow[0] * corr0 + ps[0];
        lrow[1] = lrow[1] * corr1 + ps[1];
#pragma unroll
        for (int nt = 0; nt < 8; nt++) {
            o[nt][0] *= corr0; o[nt][1] *= corr0;
            o[nt][2] *= corr1; o[nt][3] *= corr1;
        }
        mrow[0] = mnew0;
        mrow[1] = mnew1;
        __syncwarp();   // P rows of this warp visible to the whole warp

        // ---- O += P V ----
#pragma unroll 2
        for (int ks = 0; ks < 8; ks++) {
            const int kc = ks * 8 + tig;
            const uint2 A0 = pa0[kc],     A1 = pa1[kc];
            const uint2 A2 = pa0[kc + 4], A3 = pa1[kc + 4];
#pragma unroll
            for (int nt = 0; nt < 8; nt++) {
                const uint2 B0 = Vh[kc * SQ + nt * 8 + gid];
                const uint2 B1 = Vh[(kc + 4) * SQ + nt * 8 + gid];
                mma_tf32(o[nt], A0.x, A1.x, A2.x, A3.x, B0.x, B1.x);
                mma_tf32(o[nt], A0.x, A1.x, A2.x, A3.x, B0.y, B1.y);
                mma_tf32(o[nt], A0.y, A1.y, A2.y, A3.y, B0.x, B1.x);
            }
        }
    }

    // Epilogue: divide by l, write to g_att [b,t, h*64+d]
    const float inv0 = 1.0f / lrow[0];
    const float inv1 = 1.0f / lrow[1];
    const size_t r0 = (size_t)b * TLEN + q0 + wr0 + gid;
#pragma unroll
    for (int nt = 0; nt < 8; nt++) {
        const int col = h * HDIM + nt * 8 + 2 * tig;
        *(float2*)(g_att + r0 * CDIM + col) =
            make_float2(o[nt][0] * inv0, o[nt][1] * inv0);
        *(float2*)(g_att + (r0 + 8) * CDIM + col) =
            make_float2(o[nt][2] * inv1, o[nt][3] * inv1);
    }
}

// ---------------------------------------------------------------------------
// kernel_launch
// Inputs: 0:x 1:W_attn 2:b_attn 3:W_proj 4:b_proj 5:bQ 6:bK 7:bV
// ---------------------------------------------------------------------------
extern "C" void kernel_launch(void* const* d_in, const int* in_sizes, int n_in,
                              void* d_out, int out_size)
{
    const float* x      = (const float*)d_in[0];
    const float* W_attn = (const float*)d_in[1];
    const float* b_attn = (const float*)d_in[2];
    const float* W_proj = (const float*)d_in[3];
    const float* b_proj = (const float*)d_in[4];
    const float* bQ     = (const float*)d_in[5];
    const float* bK     = (const float*)d_in[6];
    const float* bV     = (const float*)d_in[7];
    float* out = (float*)d_out;

    cudaFuncSetAttribute(tc_gemm<0>, cudaFuncAttributeMaxDynamicSharedMemorySize, SMEM_GEMM);
    cudaFuncSetAttribute(tc_gemm<1>, cudaFuncAttributeMaxDynamicSharedMemorySize, SMEM_GEMM);
    cudaFuncSetAttribute(flash_mma, cudaFuncAttributeMaxDynamicSharedMemorySize, FL_SMEM);

    // 0) Transpose weights into K-major form
    {
        dim3 tb(32, 8);
        transpose_k<<<dim3(3 * CDIM / 32, CDIM / 32), tb>>>(W_attn, 0, CDIM, 3 * CDIM);
        transpose_k<<<dim3(CDIM / 32, CDIM / 32), tb>>>(W_proj, WT_PROJ_OFF, CDIM, CDIM);
    }

    // 1) QKV GEMM (tf32 mma.sync) + bias + head scatter
    {
        dim3 grid(3 * CDIM / 128, MTOT / 128);   // (24, 64)
        tc_gemm<0><<<grid, 256, SMEM_GEMM>>>(x, 0, b_attn, bQ, bK, bV, nullptr);
    }

    // 2) Causal flash attention (split-tf32, precomputed hi/lo)
    {
        dim3 grid(TLEN / QR, NHEAD, BSZ);        // (16, 16, 4)
        flash_mma<<<grid, 256, FL_SMEM>>>();
    }

    // 3) Projection GEMM (tf32 mma.sync) + b_proj
    {
        dim3 grid(CDIM / 128, MTOT / 128);       // (8, 64)
        tc_gemm<1><<<grid, 256, SMEM_GEMM>>>(nullptr, WT_PROJ_OFF, b_proj,
                                             nullptr, nullptr, nullptr, out);
    }
}

// round 10
// speedup vs baseline: 1.2163x; 1.2163x over previous
#include <cuda_runtime.h>
#include <cstdint>
#include <math.h>

// Problem constants
#define BSZ   4
#define TLEN  2048
#define CDIM  1024
#define NHEAD 16
#define HDIM  64
#define MTOT  (BSZ * TLEN)          // 8192

// ---------------------------------------------------------------------------
// Scratch (device globals — no allocation allowed)
// ---------------------------------------------------------------------------
__device__ float g_q[BSZ * NHEAD * TLEN * HDIM];   // [b,h,t,d]
__device__ float g_k[BSZ * NHEAD * TLEN * HDIM];
__device__ float g_v[BSZ * NHEAD * TLEN * HDIM];
__device__ float g_att[BSZ * TLEN * CDIM];         // [b,t,c]
__device__ float g_wT[4 * CDIM * CDIM];            // W_attn^T then W_proj^T

#define WT_PROJ_OFF (3 * CDIM * CDIM)

// ---------------------------------------------------------------------------
// Portable PTX helpers (sm_80+ only; harness targets plain sm_100)
// ---------------------------------------------------------------------------
__device__ __forceinline__ uint32_t smem_u32(const void* p) {
    uint32_t a;
    asm("{ .reg .u64 t; cvta.to.shared.u64 t, %1; cvt.u32.u64 %0, t; }" : "=r"(a) : "l"(p));
    return a;
}

#define CP_ASYNC16(dst, src) \
    asm volatile("cp.async.cg.shared.global [%0], [%1], 16;" :: "r"(dst), "l"(src))
#define CP_COMMIT() asm volatile("cp.async.commit_group;")
#define CP_WAIT(n)  asm volatile("cp.async.wait_group %0;" :: "n"(n))

__device__ __forceinline__ uint32_t swz(uint32_t off) { return off ^ ((off >> 3) & 0x70); }

__device__ __forceinline__ uint32_t f2tf32(float f) {
    uint32_t r;
    asm("cvt.rna.tf32.f32 %0, %1;" : "=r"(r) : "f"(f));
    return r;
}

// split a float into tf32 hi + tf32 lo (packed)
__device__ __forceinline__ uint2 split_tf32(float f) {
    uint2 r;
    r.x = f2tf32(f);
    r.y = f2tf32(f - __uint_as_float(r.x));
    return r;
}

// m16n8k8 tf32 mma, fp32 accumulate (sm_80+)
__device__ __forceinline__ void mma_tf32(float c[4],
                                         uint32_t a0, uint32_t a1, uint32_t a2, uint32_t a3,
                                         uint32_t b0, uint32_t b1) {
    asm volatile(
        "mma.sync.aligned.m16n8k8.row.col.f32.tf32.tf32.f32 "
        "{%0,%1,%2,%3}, {%4,%5,%6,%7}, {%8,%9}, {%0,%1,%2,%3};"
        : "+f"(c[0]), "+f"(c[1]), "+f"(c[2]), "+f"(c[3])
        : "r"(a0), "r"(a1), "r"(a2), "r"(a3), "r"(b0), "r"(b1));
}

// ---------------------------------------------------------------------------
// Weight transpose: out[c][r] = in[r][c], written into g_wT + dst_off
// ---------------------------------------------------------------------------
__global__ __launch_bounds__(256)
void transpose_k(const float* __restrict__ in, int dst_off, int R, int C)
{
    __shared__ float t[32][33];
    const int c0 = blockIdx.x * 32, r0 = blockIdx.y * 32;
    const int tx = threadIdx.x, ty = threadIdx.y;
#pragma unroll
    for (int i = ty; i < 32; i += 8)
        t[i][tx] = in[(r0 + i) * C + c0 + tx];
    __syncthreads();
#pragma unroll
    for (int i = ty; i < 32; i += 8)
        g_wT[dst_off + (c0 + i) * R + r0 + tx] = t[tx][i];
}

// ---------------------------------------------------------------------------
// tf32 mma.sync GEMM (unchanged from R4/R7, passing)
// ---------------------------------------------------------------------------
#define TK          32
#define STAGES      3
#define STAGE_BYTES 32768
#define STAGE_F     8192
#define SMEM_GEMM   (STAGES * STAGE_BYTES)

template <int MODE>
__device__ __forceinline__ void load_stage(const float* Ap, const float* Bt,
                                           uint32_t sb, int m0, int n0, int tid,
                                           int s, int k0)
{
    const uint32_t base = sb + s * STAGE_BYTES;
#pragma unroll
    for (int j = 0; j < 4; j++) {
        const int idx = tid + j * 256;
        const int r = idx >> 3, c = idx & 7;
        CP_ASYNC16(base + swz(r * 128 + c * 16), Ap + (m0 + r) * CDIM + k0 + c * 4);
    }
#pragma unroll
    for (int j = 0; j < 4; j++) {
        const int idx = tid + j * 256;
        const int r = idx >> 3, c = idx & 7;
        CP_ASYNC16(base + 16384 + swz(r * 128 + c * 16), Bt + (n0 + r) * CDIM + k0 + c * 4);
    }
}

template <int MODE>
__global__ __launch_bounds__(256, 2)
void tc_gemm(const float* __restrict__ A,
             int bt_off,
             const float* __restrict__ bias,
             const float* __restrict__ bQ,
             const float* __restrict__ bK,
             const float* __restrict__ bV,
             float* __restrict__ Cout)
{
    extern __shared__ float smemf[];
    const uint32_t sb = smem_u32(smemf);
    const int tid  = threadIdx.x;
    const int lane = tid & 31;
    const int wid  = tid >> 5;
    const int gid  = lane >> 2;
    const int tig  = lane & 3;
    const int wm   = (wid & 3) * 32;
    const int wn   = (wid >> 2) * 64;

    const int m0 = blockIdx.y * 128;
    const int n0 = blockIdx.x * 128;

    const float* Ap = (MODE == 1) ? (const float*)g_att : A;
    const float* Bt = g_wT + bt_off;

    float acc[2][8][4];
#pragma unroll
    for (int mt = 0; mt < 2; mt++)
#pragma unroll
        for (int nt = 0; nt < 8; nt++)
#pragma unroll
            for (int j = 0; j < 4; j++) acc[mt][nt][j] = 0.0f;

    load_stage<MODE>(Ap, Bt, sb, m0, n0, tid, 0, 0);
    CP_COMMIT();
    load_stage<MODE>(Ap, Bt, sb, m0, n0, tid, 1, TK);
    CP_COMMIT();

    const int NIT = CDIM / TK;
    const int xr  = gid << 2;

    int slot = 0;
    for (int i = 0; i < NIT; i++) {
        CP_WAIT(1);
        __syncthreads();

        if (i + 2 < NIT)
            load_stage<MODE>(Ap, Bt, sb, m0, n0, tid, (i + 2) % STAGES, (i + 2) * TK);
        CP_COMMIT();

        const float* As = smemf + slot * STAGE_F;
        const float* Bs = As + 4096;

#pragma unroll
        for (int ks = 0; ks < 4; ks++) {
            const int c0 = ((ks * 8) + tig) ^ xr;
            const int c4 = c0 ^ 4;

            uint32_t a[2][4];
#pragma unroll
            for (int mt = 0; mt < 2; mt++) {
                const int r0 = wm + mt * 16 + gid;
                const int r1 = r0 + 8;
                a[mt][0] = f2tf32(As[r0 * 32 + c0]);
                a[mt][1] = f2tf32(As[r1 * 32 + c0]);
                a[mt][2] = f2tf32(As[r0 * 32 + c4]);
                a[mt][3] = f2tf32(As[r1 * 32 + c4]);
            }
#pragma unroll
            for (int nt = 0; nt < 8; nt++) {
                const int n = wn + nt * 8 + gid;
                const uint32_t b0 = f2tf32(Bs[n * 32 + c0]);
                const uint32_t b1 = f2tf32(Bs[n * 32 + c4]);
                mma_tf32(acc[0][nt], a[0][0], a[0][1], a[0][2], a[0][3], b0, b1);
                mma_tf32(acc[1][nt], a[1][0], a[1][1], a[1][2], a[1][3], b0, b1);
            }
        }
        slot = (slot + 1) % STAGES;
    }

#pragma unroll
    for (int mt = 0; mt < 2; mt++) {
#pragma unroll
        for (int half = 0; half < 2; half++) {
            const int row = m0 + wm + mt * 16 + gid + half * 8;
#pragma unroll
            for (int nt = 0; nt < 8; nt++) {
                const int col = n0 + wn + nt * 8 + tig * 2;
                float v0 = acc[mt][nt][half * 2 + 0] + bias[col];
                float v1 = acc[mt][nt][half * 2 + 1] + bias[col + 1];

                if (MODE == 1) {
                    *(float2*)&Cout[(size_t)row * CDIM + col] = make_float2(v0, v1);
                } else {
                    const int sec = col >> 10;
                    const int n2  = col & 1023;
                    const float* hb = (sec == 0) ? bQ : (sec == 1) ? bK : bV;
                    v0 += hb[n2];
                    v1 += hb[n2 + 1];
                    const int h  = n2 >> 6, dd = n2 & 63;
                    const int b_ = row >> 11, t = row & (TLEN - 1);
                    float* base = (sec == 0) ? g_q : (sec == 1) ? g_k : g_v;
                    *(float2*)&base[(((size_t)(b_ * NHEAD + h) * TLEN) + t) * HDIM + dd] =
                        make_float2(v0, v1);
                }
            }
        }
    }
}

// ---------------------------------------------------------------------------
// Flash attention v4 = R7 + pre-split K/V only.
// 64 q-rows/CTA, 4 warps, 2 CTA/SM. Q and P stay RAW in SMEM and are split
// per-use (A-side, cheap, 8 splits/ks-pair); K and V are split ONCE at tile
// load into hi/lo uint2 (kills the 4x-redundant B-side conversions that were
// ~2/3 of R7's ALU traffic). Loop structure/unroll factors identical to R7
// (the only flash variant family that compiles cleanly).
// SMEM: Qraw[64][68]f + Praw[64][68]f + Khl[64][68]u2 + Vhl[64][68]u2
//     = 17408 + 17408 + 34816 + 34816 = 104448 B  -> 2 CTA/SM.
// ---------------------------------------------------------------------------
#define SQF    68                         // float row stride (Q, P)
#define SQ     68                         // uint2 row stride (K, V)
#define FL_Q   0                          // float offset
#define FL_P   (64 * SQF)                 // 4352 floats
#define FL_KB  (2 * 64 * SQF * 4)         // byte offset of Kh: 34816
#define FL_VB  (FL_KB + 64 * SQ * 8)      // byte offset of Vh: 69632
#define FL_SMEM (FL_VB + 64 * SQ * 8)     // 104448 bytes

__global__ __launch_bounds__(128, 2)
void flash_mma()
{
    extern __shared__ char flsm[];
    float* Qs = (float*)flsm;              // [64][68] raw (pre-scaled)
    float* Ps = (float*)flsm + FL_P;       // [64][68] raw
    uint2* Kh = (uint2*)(flsm + FL_KB);    // [64][68] hi/lo
    uint2* Vh = (uint2*)(flsm + FL_VB);    // [64][68] hi/lo (Vh[key][dim])

    const int tid  = threadIdx.x;
    const int lane = tid & 31;
    const int wid  = tid >> 5;
    const int gid  = lane >> 2;
    const int tig  = lane & 3;
    const int wr0  = wid * 16;

    const int qt = (int)gridDim.x - 1 - (int)blockIdx.x;   // heavy tiles first
    const int h  = blockIdx.y;
    const int b  = blockIdx.z;
    const int bh = b * NHEAD + h;
    const int q0 = qt * 64;

    // Load Q tile raw (pre-scaled by 1/sqrt(d))
    for (int idx = tid; idx < 64 * 16; idx += 128) {
        const int row = idx >> 4, c = (idx & 15) * 4;
        float4 v = *(const float4*)(g_q + ((size_t)bh * TLEN + q0 + row) * HDIM + c);
        *(float4*)(Qs + row * SQF + c) =
            make_float4(v.x * 0.125f, v.y * 0.125f, v.z * 0.125f, v.w * 0.125f);
    }

    float o[8][4];
#pragma unroll
    for (int nt = 0; nt < 8; nt++)
#pragma unroll
        for (int j = 0; j < 4; j++) o[nt][j] = 0.0f;
    float mrow[2] = {-1e30f, -1e30f};
    float lrow[2] = {0.0f, 0.0f};

    for (int kt = 0; kt <= qt; kt++) {
        __syncthreads();   // previous iteration done with Kh/Vh/Ps
        for (int idx = tid; idx < 64 * 16; idx += 128) {
            const int row = idx >> 4, c = (idx & 15) * 4;
            const size_t src = ((size_t)bh * TLEN + kt * 64 + row) * HDIM + c;
            float4 kv = *(const float4*)(g_k + src);
            float4 vv = *(const float4*)(g_v + src);
            uint2* kd = Kh + row * SQ + c;
            kd[0] = split_tf32(kv.x); kd[1] = split_tf32(kv.y);
            kd[2] = split_tf32(kv.z); kd[3] = split_tf32(kv.w);
            uint2* vd = Vh + row * SQ + c;
            vd[0] = split_tf32(vv.x); vd[1] = split_tf32(vv.y);
            vd[2] = split_tf32(vv.z); vd[3] = split_tf32(vv.w);
        }
        __syncthreads();

        // ---- S = Q K^T (A split per-use, B pre-split) ----
        float s[8][4];
#pragma unroll
        for (int nt = 0; nt < 8; nt++)
#pragma unroll
            for (int j = 0; j < 4; j++) s[nt][j] = 0.0f;

#pragma unroll 2
        for (int ks = 0; ks < 8; ks++) {
            const int kc = ks * 8 + tig;
            const uint2 A0 = split_tf32(Qs[(wr0 + gid) * SQF + kc]);
            const uint2 A1 = split_tf32(Qs[(wr0 + gid + 8) * SQF + kc]);
            const uint2 A2 = split_tf32(Qs[(wr0 + gid) * SQF + kc + 4]);
            const uint2 A3 = split_tf32(Qs[(wr0 + gid + 8) * SQF + kc + 4]);
#pragma unroll
            for (int nt = 0; nt < 8; nt++) {
                const uint2 B0 = Kh[(nt * 8 + gid) * SQ + kc];
                const uint2 B1 = Kh[(nt * 8 + gid) * SQ + kc + 4];
                mma_tf32(s[nt], A0.x, A1.x, A2.x, A3.x, B0.x, B1.x);
                mma_tf32(s[nt], A0.x, A1.x, A2.x, A3.x, B0.y, B1.y);
                mma_tf32(s[nt], A0.y, A1.y, A2.y, A3.y, B0.x, B1.x);
            }
        }

        // Causal mask (diagonal tile only)
        if (kt == qt) {
#pragma unroll
            for (int nt = 0; nt < 8; nt++) {
#pragma unroll
                for (int j = 0; j < 4; j++) {
                    const int col = nt * 8 + 2 * tig + (j & 1);
                    const int row = wr0 + gid + (j >> 1) * 8;
                    if (col > row) s[nt][j] = -1e30f;
                }
            }
        }

        // Row max (quad reduction over tig)
        float tmax[2] = {-1e30f, -1e30f};
#pragma unroll
        for (int nt = 0; nt < 8; nt++) {
            tmax[0] = fmaxf(tmax[0], fmaxf(s[nt][0], s[nt][1]));
            tmax[1] = fmaxf(tmax[1], fmaxf(s[nt][2], s[nt][3]));
        }
#pragma unroll
        for (int d = 1; d <= 2; d <<= 1) {
            tmax[0] = fmaxf(tmax[0], __shfl_xor_sync(0xFFFFFFFFu, tmax[0], d));
            tmax[1] = fmaxf(tmax[1], __shfl_xor_sync(0xFFFFFFFFu, tmax[1], d));
        }
        const float mnew0 = fmaxf(mrow[0], tmax[0]);
        const float mnew1 = fmaxf(mrow[1], tmax[1]);
        const float corr0 = __expf(mrow[0] - mnew0);
        const float corr1 = __expf(mrow[1] - mnew1);

        // p = exp(s - m), row sums, stage raw P to SMEM
        float ps[2] = {0.0f, 0.0f};
#pragma unroll
        for (int nt = 0; nt < 8; nt++) {
            const float p0 = __expf(s[nt][0] - mnew0);
            const float p1 = __expf(s[nt][1] - mnew0);
            const float p2 = __expf(s[nt][2] - mnew1);
            const float p3 = __expf(s[nt][3] - mnew1);
            ps[0] += p0 + p1;
            ps[1] += p2 + p3;
            *(float2*)(Ps + (wr0 + gid) * SQF + nt * 8 + 2 * tig)     = make_float2(p0, p1);
            *(float2*)(Ps + (wr0 + gid + 8) * SQF + nt * 8 + 2 * tig) = make_float2(p2, p3);
        }
#pragma unroll
        for (int d = 1; d <= 2; d <<= 1) {
            ps[0] += __shfl_xor_sync(0xFFFFFFFFu, ps[0], d);
            ps[1] += __shfl_xor_sync(0xFFFFFFFFu, ps[1], d);
        }
        lrow[0] = lrow[0] * corr0 + ps[0];
        lrow[1] = lrow[1] * corr1 + ps[1];
#pragma unroll
        for (int nt = 0; nt < 8; nt++) {
            o[nt][0] *= corr0; o[nt][1] *= corr0;
            o[nt][2] *= corr1; o[nt][3] *= corr1;
        }
        mrow[0] = mnew0;
        mrow[1] = mnew1;
        __syncwarp();   // P rows of this warp visible to the whole warp

        // ---- O += P V (A split per-use, B pre-split) ----
#pragma unroll 2
        for (int ks = 0; ks < 8; ks++) {
            const int kc = ks * 8 + tig;
            const uint2 A0 = split_tf32(Ps[(wr0 + gid) * SQF + kc]);
            const uint2 A1 = split_tf32(Ps[(wr0 + gid + 8) * SQF + kc]);
            const uint2 A2 = split_tf32(Ps[(wr0 + gid) * SQF + kc + 4]);
            const uint2 A3 = split_tf32(Ps[(wr0 + gid + 8) * SQF + kc + 4]);
#pragma unroll
            for (int nt = 0; nt < 8; nt++) {
                const uint2 B0 = Vh[kc * SQ + nt * 8 + gid];
                const uint2 B1 = Vh[(kc + 4) * SQ + nt * 8 + gid];
                mma_tf32(o[nt], A0.x, A1.x, A2.x, A3.x, B0.x, B1.x);
                mma_tf32(o[nt], A0.x, A1.x, A2.x, A3.x, B0.y, B1.y);
                mma_tf32(o[nt], A0.y, A1.y, A2.y, A3.y, B0.x, B1.x);
            }
        }
    }

    // Epilogue: divide by l, write to g_att [b,t, h*64+d]
    const float inv0 = 1.0f / lrow[0];
    const float inv1 = 1.0f / lrow[1];
    const size_t r0 = (size_t)b * TLEN + q0 + wr0 + gid;
#pragma unroll
    for (int nt = 0; nt < 8; nt++) {
        const int col = h * HDIM + nt * 8 + 2 * tig;
        *(float2*)(g_att + r0 * CDIM + col) =
            make_float2(o[nt][0] * inv0, o[nt][1] * inv0);
        *(float2*)(g_att + (r0 + 8) * CDIM + col) =
            make_float2(o[nt][2] * inv1, o[nt][3] * inv1);
    }
}

// ---------------------------------------------------------------------------
// kernel_launch
// Inputs: 0:x 1:W_attn 2:b_attn 3:W_proj 4:b_proj 5:bQ 6:bK 7:bV
// ---------------------------------------------------------------------------
extern "C" void kernel_launch(void* const* d_in, const int* in_sizes, int n_in,
                              void* d_out, int out_size)
{
    const float* x      = (const float*)d_in[0];
    const float* W_attn = (const float*)d_in[1];
    const float* b_attn = (const float*)d_in[2];
    const float* W_proj = (const float*)d_in[3];
    const float* b_proj = (const float*)d_in[4];
    const float* bQ     = (const float*)d_in[5];
    const float* bK     = (const float*)d_in[6];
    const float* bV     = (const float*)d_in[7];
    float* out = (float*)d_out;

    cudaFuncSetAttribute(tc_gemm<0>, cudaFuncAttributeMaxDynamicSharedMemorySize, SMEM_GEMM);
    cudaFuncSetAttribute(tc_gemm<1>, cudaFuncAttributeMaxDynamicSharedMemorySize, SMEM_GEMM);
    cudaFuncSetAttribute(flash_mma, cudaFuncAttributeMaxDynamicSharedMemorySize, FL_SMEM);

    // 0) Transpose weights into K-major form
    {
        dim3 tb(32, 8);
        transpose_k<<<dim3(3 * CDIM / 32, CDIM / 32), tb>>>(W_attn, 0, CDIM, 3 * CDIM);
        transpose_k<<<dim3(CDIM / 32, CDIM / 32), tb>>>(W_proj, WT_PROJ_OFF, CDIM, CDIM);
    }

    // 1) QKV GEMM (tf32 mma.sync) + bias + head scatter
    {
        dim3 grid(3 * CDIM / 128, MTOT / 128);   // (24, 64)
        tc_gemm<0><<<grid, 256, SMEM_GEMM>>>(x, 0, b_attn, bQ, bK, bV, nullptr);
    }

    // 2) Causal flash attention (split-tf32, K/V pre-split)
    {
        dim3 grid(TLEN / 64, NHEAD, BSZ);        // (32, 16, 4)
        flash_mma<<<grid, 128, FL_SMEM>>>();
    }

    // 3) Projection GEMM (tf32 mma.sync) + b_proj
    {
        dim3 grid(CDIM / 128, MTOT / 128);       // (8, 64)
        tc_gemm<1><<<grid, 256, SMEM_GEMM>>>(nullptr, WT_PROJ_OFF, b_proj,
                                             nullptr, nullptr, nullptr, out);
    }
}

// round 13
// speedup vs baseline: 1.5458x; 1.2709x over previous
#include <cuda_runtime.h>
#include <cstdint>
#include <math.h>

// Problem constants
#define BSZ   4
#define TLEN  2048
#define CDIM  1024
#define NHEAD 16
#define HDIM  64
#define MTOT  (BSZ * TLEN)          // 8192

// ---------------------------------------------------------------------------
// Scratch (device globals — no allocation allowed)
// ---------------------------------------------------------------------------
__device__ float g_q[BSZ * NHEAD * TLEN * HDIM];   // [b,h,t,d]
__device__ float g_k[BSZ * NHEAD * TLEN * HDIM];
__device__ float g_v[BSZ * NHEAD * TLEN * HDIM];
__device__ float g_att[BSZ * TLEN * CDIM];         // [b,t,c]
__device__ float g_wT[4 * CDIM * CDIM];            // W_attn^T then W_proj^T

#define WT_PROJ_OFF (3 * CDIM * CDIM)

// ---------------------------------------------------------------------------
// Portable PTX helpers (sm_80+ only; harness targets plain sm_100)
// ---------------------------------------------------------------------------
__device__ __forceinline__ uint32_t smem_u32(const void* p) {
    uint32_t a;
    asm("{ .reg .u64 t; cvta.to.shared.u64 t, %1; cvt.u32.u64 %0, t; }" : "=r"(a) : "l"(p));
    return a;
}

#define CP_ASYNC16(dst, src) \
    asm volatile("cp.async.cg.shared.global [%0], [%1], 16;" :: "r"(dst), "l"(src))
#define CP_COMMIT() asm volatile("cp.async.commit_group;")
#define CP_WAIT(n)  asm volatile("cp.async.wait_group %0;" :: "n"(n))

__device__ __forceinline__ uint32_t swz(uint32_t off) { return off ^ ((off >> 3) & 0x70); }

__device__ __forceinline__ uint32_t f2tf32(float f) {
    uint32_t r;
    asm("cvt.rna.tf32.f32 %0, %1;" : "=r"(r) : "f"(f));
    return r;
}

// split a float into tf32 hi + tf32 lo (packed)
__device__ __forceinline__ uint2 split_tf32(float f) {
    uint2 r;
    r.x = f2tf32(f);
    r.y = f2tf32(f - __uint_as_float(r.x));
    return r;
}

// m16n8k8 tf32 mma, fp32 accumulate (sm_80+)
__device__ __forceinline__ void mma_tf32(float c[4],
                                         uint32_t a0, uint32_t a1, uint32_t a2, uint32_t a3,
                                         uint32_t b0, uint32_t b1) {
    asm volatile(
        "mma.sync.aligned.m16n8k8.row.col.f32.tf32.tf32.f32 "
        "{%0,%1,%2,%3}, {%4,%5,%6,%7}, {%8,%9}, {%0,%1,%2,%3};"
        : "+f"(c[0]), "+f"(c[1]), "+f"(c[2]), "+f"(c[3])
        : "r"(a0), "r"(a1), "r"(a2), "r"(a3), "r"(b0), "r"(b1));
}

// ---------------------------------------------------------------------------
// Weight transpose: out[c][r] = in[r][c], written into g_wT + dst_off
// ---------------------------------------------------------------------------
__global__ __launch_bounds__(256)
void transpose_k(const float* __restrict__ in, int dst_off, int R, int C)
{
    __shared__ float t[32][33];
    const int c0 = blockIdx.x * 32, r0 = blockIdx.y * 32;
    const int tx = threadIdx.x, ty = threadIdx.y;
#pragma unroll
    for (int i = ty; i < 32; i += 8)
        t[i][tx] = in[(r0 + i) * C + c0 + tx];
    __syncthreads();
#pragma unroll
    for (int i = ty; i < 32; i += 8)
        g_wT[dst_off + (c0 + i) * R + r0 + tx] = t[tx][i];
}

// ---------------------------------------------------------------------------
// tf32 mma.sync GEMM (unchanged from R4/R7, passing)
// ---------------------------------------------------------------------------
#define TK          32
#define STAGES      3
#define STAGE_BYTES 32768
#define STAGE_F     8192
#define SMEM_GEMM   (STAGES * STAGE_BYTES)

template <int MODE>
__device__ __forceinline__ void load_stage(const float* Ap, const float* Bt,
                                           uint32_t sb, int m0, int n0, int tid,
                                           int s, int k0)
{
    const uint32_t base = sb + s * STAGE_BYTES;
#pragma unroll
    for (int j = 0; j < 4; j++) {
        const int idx = tid + j * 256;
        const int r = idx >> 3, c = idx & 7;
        CP_ASYNC16(base + swz(r * 128 + c * 16), Ap + (m0 + r) * CDIM + k0 + c * 4);
    }
#pragma unroll
    for (int j = 0; j < 4; j++) {
        const int idx = tid + j * 256;
        const int r = idx >> 3, c = idx & 7;
        CP_ASYNC16(base + 16384 + swz(r * 128 + c * 16), Bt + (n0 + r) * CDIM + k0 + c * 4);
    }
}

template <int MODE>
__global__ __launch_bounds__(256, 2)
void tc_gemm(const float* __restrict__ A,
             int bt_off,
             const float* __restrict__ bias,
             const float* __restrict__ bQ,
             const float* __restrict__ bK,
             const float* __restrict__ bV,
             float* __restrict__ Cout)
{
    extern __shared__ float smemf[];
    const uint32_t sb = smem_u32(smemf);
    const int tid  = threadIdx.x;
    const int lane = tid & 31;
    const int wid  = tid >> 5;
    const int gid  = lane >> 2;
    const int tig  = lane & 3;
    const int wm   = (wid & 3) * 32;
    const int wn   = (wid >> 2) * 64;

    const int m0 = blockIdx.y * 128;
    const int n0 = blockIdx.x * 128;

    const float* Ap = (MODE == 1) ? (const float*)g_att : A;
    const float* Bt = g_wT + bt_off;

    float acc[2][8][4];
#pragma unroll
    for (int mt = 0; mt < 2; mt++)
#pragma unroll
        for (int nt = 0; nt < 8; nt++)
#pragma unroll
            for (int j = 0; j < 4; j++) acc[mt][nt][j] = 0.0f;

    load_stage<MODE>(Ap, Bt, sb, m0, n0, tid, 0, 0);
    CP_COMMIT();
    load_stage<MODE>(Ap, Bt, sb, m0, n0, tid, 1, TK);
    CP_COMMIT();

    const int NIT = CDIM / TK;
    const int xr  = gid << 2;

    int slot = 0;
    for (int i = 0; i < NIT; i++) {
        CP_WAIT(1);
        __syncthreads();

        if (i + 2 < NIT)
            load_stage<MODE>(Ap, Bt, sb, m0, n0, tid, (i + 2) % STAGES, (i + 2) * TK);
        CP_COMMIT();

        const float* As = smemf + slot * STAGE_F;
        const float* Bs = As + 4096;

#pragma unroll
        for (int ks = 0; ks < 4; ks++) {
            const int c0 = ((ks * 8) + tig) ^ xr;
            const int c4 = c0 ^ 4;

            uint32_t a[2][4];
#pragma unroll
            for (int mt = 0; mt < 2; mt++) {
                const int r0 = wm + mt * 16 + gid;
                const int r1 = r0 + 8;
                a[mt][0] = f2tf32(As[r0 * 32 + c0]);
                a[mt][1] = f2tf32(As[r1 * 32 + c0]);
                a[mt][2] = f2tf32(As[r0 * 32 + c4]);
                a[mt][3] = f2tf32(As[r1 * 32 + c4]);
            }
#pragma unroll
            for (int nt = 0; nt < 8; nt++) {
                const int n = wn + nt * 8 + gid;
                const uint32_t b0 = f2tf32(Bs[n * 32 + c0]);
                const uint32_t b1 = f2tf32(Bs[n * 32 + c4]);
                mma_tf32(acc[0][nt], a[0][0], a[0][1], a[0][2], a[0][3], b0, b1);
                mma_tf32(acc[1][nt], a[1][0], a[1][1], a[1][2], a[1][3], b0, b1);
            }
        }
        slot = (slot + 1) % STAGES;
    }

#pragma unroll
    for (int mt = 0; mt < 2; mt++) {
#pragma unroll
        for (int half = 0; half < 2; half++) {
            const int row = m0 + wm + mt * 16 + gid + half * 8;
#pragma unroll
            for (int nt = 0; nt < 8; nt++) {
                const int col = n0 + wn + nt * 8 + tig * 2;
                float v0 = acc[mt][nt][half * 2 + 0] + bias[col];
                float v1 = acc[mt][nt][half * 2 + 1] + bias[col + 1];

                if (MODE == 1) {
                    *(float2*)&Cout[(size_t)row * CDIM + col] = make_float2(v0, v1);
                } else {
                    const int sec = col >> 10;
                    const int n2  = col & 1023;
                    const float* hb = (sec == 0) ? bQ : (sec == 1) ? bK : bV;
                    v0 += hb[n2];
                    v1 += hb[n2 + 1];
                    const int h  = n2 >> 6, dd = n2 & 63;
                    const int b_ = row >> 11, t = row & (TLEN - 1);
                    float* base = (sec == 0) ? g_q : (sec == 1) ? g_k : g_v;
                    *(float2*)&base[(((size_t)(b_ * NHEAD + h) * TLEN) + t) * HDIM + dd] =
                        make_float2(v0, v1);
                }
            }
        }
    }
}

// ---------------------------------------------------------------------------
// Flash attention v6 = R7 exactly, except PV uses plain tf32 (1 mma, not 3).
// S = QK^T stays 3xTF32 (softmax amplifies S errors); P in [0,1] and V ~O(1)
// tolerate 2^-12 relative rounding -> predicted rel_err ~6e-4 < 1e-3.
// 64 q-rows/CTA, 4 warps, 70656 B smem (R7's proven config).
// RESUBMISSION of R12 verbatim: flash body is a strict subset of passing R7,
// so the R12 "container failed twice" is attributed to infra flake, not code.
// ---------------------------------------------------------------------------
#define FL_SMEM (17664 * 4)   // Qs 4352 + Ks 4352 + Vs 4608 + Ps 4352 floats

__global__ __launch_bounds__(128, 2)
void flash_mma()
{
    extern __shared__ float sm[];
    float* Qs = sm;            // [64][68]
    float* Ks = sm + 4352;     // [64][68]
    float* Vs = sm + 8704;     // [64][72]   (Vs[key][dim])
    float* Ps = sm + 13312;    // [64][68]

    const int tid  = threadIdx.x;
    const int lane = tid & 31;
    const int wid  = tid >> 5;
    const int gid  = lane >> 2;
    const int tig  = lane & 3;
    const int wr0  = wid * 16;

    const int qt = (int)gridDim.x - 1 - (int)blockIdx.x;   // heavy tiles first
    const int h  = blockIdx.y;
    const int b  = blockIdx.z;
    const int bh = b * NHEAD + h;
    const int q0 = qt * 64;

    // Load Q tile (pre-scaled by 1/sqrt(d))
    for (int idx = tid; idx < 64 * 16; idx += 128) {
        const int row = idx >> 4, c = (idx & 15) * 4;
        float4 v = *(const float4*)(g_q + ((size_t)bh * TLEN + q0 + row) * HDIM + c);
        *(float4*)(Qs + row * 68 + c) =
            make_float4(v.x * 0.125f, v.y * 0.125f, v.z * 0.125f, v.w * 0.125f);
    }

    float o[8][4];
#pragma unroll
    for (int nt = 0; nt < 8; nt++)
#pragma unroll
        for (int j = 0; j < 4; j++) o[nt][j] = 0.0f;
    float mrow[2] = {-1e30f, -1e30f};
    float lrow[2] = {0.0f, 0.0f};

    for (int kt = 0; kt <= qt; kt++) {
        __syncthreads();   // previous iteration done with Ks/Vs/Ps
        for (int idx = tid; idx < 64 * 16; idx += 128) {
            const int row = idx >> 4, c = (idx & 15) * 4;
            const size_t src = ((size_t)bh * TLEN + kt * 64 + row) * HDIM + c;
            *(float4*)(Ks + row * 68 + c) = *(const float4*)(g_k + src);
            *(float4*)(Vs + row * 72 + c) = *(const float4*)(g_v + src);
        }
        __syncthreads();

        // ---- S = Q K^T (split tf32, 3 mma) ----
        float s[8][4];
#pragma unroll
        for (int nt = 0; nt < 8; nt++)
#pragma unroll
            for (int j = 0; j < 4; j++) s[nt][j] = 0.0f;

#pragma unroll 2
        for (int ks = 0; ks < 8; ks++) {
            const int kc = ks * 8 + tig;
            float af[4];
            af[0] = Qs[(wr0 + gid) * 68 + kc];
            af[1] = Qs[(wr0 + gid + 8) * 68 + kc];
            af[2] = Qs[(wr0 + gid) * 68 + kc + 4];
            af[3] = Qs[(wr0 + gid + 8) * 68 + kc + 4];
            uint32_t ah[4], al[4];
#pragma unroll
            for (int j = 0; j < 4; j++) {
                ah[j] = f2tf32(af[j]);
                al[j] = f2tf32(af[j] - __uint_as_float(ah[j]));
            }
#pragma unroll
            for (int nt = 0; nt < 8; nt++) {
                const float b0f = Ks[(nt * 8 + gid) * 68 + kc];
                const float b1f = Ks[(nt * 8 + gid) * 68 + kc + 4];
                const uint32_t bh0 = f2tf32(b0f);
                const uint32_t bh1 = f2tf32(b1f);
                const uint32_t bl0 = f2tf32(b0f - __uint_as_float(bh0));
                const uint32_t bl1 = f2tf32(b1f - __uint_as_float(bh1));
                mma_tf32(s[nt], ah[0], ah[1], ah[2], ah[3], bh0, bh1);
                mma_tf32(s[nt], ah[0], ah[1], ah[2], ah[3], bl0, bl1);
                mma_tf32(s[nt], al[0], al[1], al[2], al[3], bh0, bh1);
            }
        }

        // Causal mask (only the diagonal tile)
        if (kt == qt) {
#pragma unroll
            for (int nt = 0; nt < 8; nt++) {
#pragma unroll
                for (int j = 0; j < 4; j++) {
                    const int col = nt * 8 + 2 * tig + (j & 1);
                    const int row = wr0 + gid + (j >> 1) * 8;
                    if (col > row) s[nt][j] = -1e30f;
                }
            }
        }

        // Row max over tile (quad reduction)
        float tmax[2] = {-1e30f, -1e30f};
#pragma unroll
        for (int nt = 0; nt < 8; nt++) {
            tmax[0] = fmaxf(tmax[0], fmaxf(s[nt][0], s[nt][1]));
            tmax[1] = fmaxf(tmax[1], fmaxf(s[nt][2], s[nt][3]));
        }
#pragma unroll
        for (int d = 1; d <= 2; d <<= 1) {
            tmax[0] = fmaxf(tmax[0], __shfl_xor_sync(0xFFFFFFFFu, tmax[0], d));
            tmax[1] = fmaxf(tmax[1], __shfl_xor_sync(0xFFFFFFFFu, tmax[1], d));
        }
        const float mnew0 = fmaxf(mrow[0], tmax[0]);
        const float mnew1 = fmaxf(mrow[1], tmax[1]);
        const float corr0 = __expf(mrow[0] - mnew0);
        const float corr1 = __expf(mrow[1] - mnew1);

        // p = exp(s - m), row sums, stage P to SMEM
        float ps[2] = {0.0f, 0.0f};
#pragma unroll
        for (int nt = 0; nt < 8; nt++) {
            const float p0 = __expf(s[nt][0] - mnew0);
            const float p1 = __expf(s[nt][1] - mnew0);
            const float p2 = __expf(s[nt][2] - mnew1);
            const float p3 = __expf(s[nt][3] - mnew1);
            ps[0] += p0 + p1;
            ps[1] += p2 + p3;
            *(float2*)(Ps + (wr0 + gid) * 68 + nt * 8 + 2 * tig)     = make_float2(p0, p1);
            *(float2*)(Ps + (wr0 + gid + 8) * 68 + nt * 8 + 2 * tig) = make_float2(p2, p3);
        }
#pragma unroll
        for (int d = 1; d <= 2; d <<= 1) {
            ps[0] += __shfl_xor_sync(0xFFFFFFFFu, ps[0], d);
            ps[1] += __shfl_xor_sync(0xFFFFFFFFu, ps[1], d);
        }
        lrow[0] = lrow[0] * corr0 + ps[0];
        lrow[1] = lrow[1] * corr1 + ps[1];
#pragma unroll
        for (int nt = 0; nt < 8; nt++) {
            o[nt][0] *= corr0; o[nt][1] *= corr0;
            o[nt][2] *= corr1; o[nt][3] *= corr1;
        }
        mrow[0] = mnew0;
        mrow[1] = mnew1;
        __syncwarp();   // P rows of this warp visible to the whole warp

        // ---- O += P V (plain tf32: P in [0,1], V ~O(1) -> 2^-12 rel noise) ----
#pragma unroll 2
        for (int ks = 0; ks < 8; ks++) {
            const int kc = ks * 8 + tig;
            const uint32_t A0 = f2tf32(Ps[(wr0 + gid) * 68 + kc]);
            const uint32_t A1 = f2tf32(Ps[(wr0 + gid + 8) * 68 + kc]);
            const uint32_t A2 = f2tf32(Ps[(wr0 + gid) * 68 + kc + 4]);
            const uint32_t A3 = f2tf32(Ps[(wr0 + gid + 8) * 68 + kc + 4]);
#pragma unroll
            for (int nt = 0; nt < 8; nt++) {
                const uint32_t B0 = f2tf32(Vs[kc * 72 + nt * 8 + gid]);
                const uint32_t B1 = f2tf32(Vs[(kc + 4) * 72 + nt * 8 + gid]);
                mma_tf32(o[nt], A0, A1, A2, A3, B0, B1);
            }
        }
    }

    // Epilogue: divide by l, write to g_att [b,t, h*64+d]
    const float inv0 = 1.0f / lrow[0];
    const float inv1 = 1.0f / lrow[1];
    const size_t r0 = (size_t)b * TLEN + q0 + wr0 + gid;
#pragma unroll
    for (int nt = 0; nt < 8; nt++) {
        const int col = h * HDIM + nt * 8 + 2 * tig;
        *(float2*)(g_att + r0 * CDIM + col) =
            make_float2(o[nt][0] * inv0, o[nt][1] * inv0);
        *(float2*)(g_att + (r0 + 8) * CDIM + col) =
            make_float2(o[nt][2] * inv1, o[nt][3] * inv1);
    }
}

// ---------------------------------------------------------------------------
// kernel_launch
// Inputs: 0:x 1:W_attn 2:b_attn 3:W_proj 4:b_proj 5:bQ 6:bK 7:bV
// ---------------------------------------------------------------------------
extern "C" void kernel_launch(void* const* d_in, const int* in_sizes, int n_in,
                              void* d_out, int out_size)
{
    const float* x      = (const float*)d_in[0];
    const float* W_attn = (const float*)d_in[1];
    const float* b_attn = (const float*)d_in[2];
    const float* W_proj = (const float*)d_in[3];
    const float* b_proj = (const float*)d_in[4];
    const float* bQ     = (const float*)d_in[5];
    const float* bK     = (const float*)d_in[6];
    const float* bV     = (const float*)d_in[7];
    float* out = (float*)d_out;

    cudaFuncSetAttribute(tc_gemm<0>, cudaFuncAttributeMaxDynamicSharedMemorySize, SMEM_GEMM);
    cudaFuncSetAttribute(tc_gemm<1>, cudaFuncAttributeMaxDynamicSharedMemorySize, SMEM_GEMM);
    cudaFuncSetAttribute(flash_mma, cudaFuncAttributeMaxDynamicSharedMemorySize, FL_SMEM);

    // 0) Transpose weights into K-major form
    {
        dim3 tb(32, 8);
        transpose_k<<<dim3(3 * CDIM / 32, CDIM / 32), tb>>>(W_attn, 0, CDIM, 3 * CDIM);
        transpose_k<<<dim3(CDIM / 32, CDIM / 32), tb>>>(W_proj, WT_PROJ_OFF, CDIM, CDIM);
    }

    // 1) QKV GEMM (tf32 mma.sync) + bias + head scatter
    {
        dim3 grid(3 * CDIM / 128, MTOT / 128);   // (24, 64)
        tc_gemm<0><<<grid, 256, SMEM_GEMM>>>(x, 0, b_attn, bQ, bK, bV, nullptr);
    }

    // 2) Causal flash attention (split-tf32 S, plain-tf32 PV)
    {
        dim3 grid(TLEN / 64, NHEAD, BSZ);        // (32, 16, 4)
        flash_mma<<<grid, 128, FL_SMEM>>>();
    }

    // 3) Projection GEMM (tf32 mma.sync) + b_proj
    {
        dim3 grid(CDIM / 128, MTOT / 128);       // (8, 64)
        tc_gemm<1><<<grid, 256, SMEM_GEMM>>>(nullptr, WT_PROJ_OFF, b_proj,
                                             nullptr, nullptr, nullptr, out);
    }
}

// round 14
// speedup vs baseline: 1.8138x; 1.1734x over previous
#include <cuda_runtime.h>
#include <cstdint>
#include <math.h>

// Problem constants
#define BSZ   4
#define TLEN  2048
#define CDIM  1024
#define NHEAD 16
#define HDIM  64
#define MTOT  (BSZ * TLEN)          // 8192

// ---------------------------------------------------------------------------
// Scratch (device globals — no allocation allowed)
// ---------------------------------------------------------------------------
__device__ float g_q[BSZ * NHEAD * TLEN * HDIM];   // [b,h,t,d]
__device__ float g_k[BSZ * NHEAD * TLEN * HDIM];
__device__ float g_v[BSZ * NHEAD * TLEN * HDIM];
__device__ float g_att[BSZ * TLEN * CDIM];         // [b,t,c]
__device__ float g_wT[4 * CDIM * CDIM];            // W_attn^T then W_proj^T

#define WT_PROJ_OFF (3 * CDIM * CDIM)

// ---------------------------------------------------------------------------
// Portable PTX helpers (sm_80+ only; harness targets plain sm_100)
// ---------------------------------------------------------------------------
__device__ __forceinline__ uint32_t smem_u32(const void* p) {
    uint32_t a;
    asm("{ .reg .u64 t; cvta.to.shared.u64 t, %1; cvt.u32.u64 %0, t; }" : "=r"(a) : "l"(p));
    return a;
}

#define CP_ASYNC16(dst, src) \
    asm volatile("cp.async.cg.shared.global [%0], [%1], 16;" :: "r"(dst), "l"(src))
#define CP_COMMIT() asm volatile("cp.async.commit_group;")
#define CP_WAIT(n)  asm volatile("cp.async.wait_group %0;" :: "n"(n))

__device__ __forceinline__ uint32_t swz(uint32_t off) { return off ^ ((off >> 3) & 0x70); }

__device__ __forceinline__ uint32_t f2tf32(float f) {
    uint32_t r;
    asm("cvt.rna.tf32.f32 %0, %1;" : "=r"(r) : "f"(f));
    return r;
}

// m16n8k8 tf32 mma, fp32 accumulate (sm_80+)
__device__ __forceinline__ void mma_tf32(float c[4],
                                         uint32_t a0, uint32_t a1, uint32_t a2, uint32_t a3,
                                         uint32_t b0, uint32_t b1) {
    asm volatile(
        "mma.sync.aligned.m16n8k8.row.col.f32.tf32.tf32.f32 "
        "{%0,%1,%2,%3}, {%4,%5,%6,%7}, {%8,%9}, {%0,%1,%2,%3};"
        : "+f"(c[0]), "+f"(c[1]), "+f"(c[2]), "+f"(c[3])
        : "r"(a0), "r"(a1), "r"(a2), "r"(a3), "r"(b0), "r"(b1));
}

// ---------------------------------------------------------------------------
// Weight transpose: out[c][r] = in[r][c], written into g_wT + dst_off
// ---------------------------------------------------------------------------
__global__ __launch_bounds__(256)
void transpose_k(const float* __restrict__ in, int dst_off, int R, int C)
{
    __shared__ float t[32][33];
    const int c0 = blockIdx.x * 32, r0 = blockIdx.y * 32;
    const int tx = threadIdx.x, ty = threadIdx.y;
#pragma unroll
    for (int i = ty; i < 32; i += 8)
        t[i][tx] = in[(r0 + i) * C + c0 + tx];
    __syncthreads();
#pragma unroll
    for (int i = ty; i < 32; i += 8)
        g_wT[dst_off + (c0 + i) * R + r0 + tx] = t[tx][i];
}

// ---------------------------------------------------------------------------
// tf32 mma.sync GEMM (unchanged from R4/R7/R13, passing)
// ---------------------------------------------------------------------------
#define TK          32
#define STAGES      3
#define STAGE_BYTES 32768
#define STAGE_F     8192
#define SMEM_GEMM   (STAGES * STAGE_BYTES)

template <int MODE>
__device__ __forceinline__ void load_stage(const float* Ap, const float* Bt,
                                           uint32_t sb, int m0, int n0, int tid,
                                           int s, int k0)
{
    const uint32_t base = sb + s * STAGE_BYTES;
#pragma unroll
    for (int j = 0; j < 4; j++) {
        const int idx = tid + j * 256;
        const int r = idx >> 3, c = idx & 7;
        CP_ASYNC16(base + swz(r * 128 + c * 16), Ap + (m0 + r) * CDIM + k0 + c * 4);
    }
#pragma unroll
    for (int j = 0; j < 4; j++) {
        const int idx = tid + j * 256;
        const int r = idx >> 3, c = idx & 7;
        CP_ASYNC16(base + 16384 + swz(r * 128 + c * 16), Bt + (n0 + r) * CDIM + k0 + c * 4);
    }
}

template <int MODE>
__global__ __launch_bounds__(256, 2)
void tc_gemm(const float* __restrict__ A,
             int bt_off,
             const float* __restrict__ bias,
             const float* __restrict__ bQ,
             const float* __restrict__ bK,
             const float* __restrict__ bV,
             float* __restrict__ Cout)
{
    extern __shared__ float smemf[];
    const uint32_t sb = smem_u32(smemf);
    const int tid  = threadIdx.x;
    const int lane = tid & 31;
    const int wid  = tid >> 5;
    const int gid  = lane >> 2;
    const int tig  = lane & 3;
    const int wm   = (wid & 3) * 32;
    const int wn   = (wid >> 2) * 64;

    const int m0 = blockIdx.y * 128;
    const int n0 = blockIdx.x * 128;

    const float* Ap = (MODE == 1) ? (const float*)g_att : A;
    const float* Bt = g_wT + bt_off;

    float acc[2][8][4];
#pragma unroll
    for (int mt = 0; mt < 2; mt++)
#pragma unroll
        for (int nt = 0; nt < 8; nt++)
#pragma unroll
            for (int j = 0; j < 4; j++) acc[mt][nt][j] = 0.0f;

    load_stage<MODE>(Ap, Bt, sb, m0, n0, tid, 0, 0);
    CP_COMMIT();
    load_stage<MODE>(Ap, Bt, sb, m0, n0, tid, 1, TK);
    CP_COMMIT();

    const int NIT = CDIM / TK;
    const int xr  = gid << 2;

    int slot = 0;
    for (int i = 0; i < NIT; i++) {
        CP_WAIT(1);
        __syncthreads();

        if (i + 2 < NIT)
            load_stage<MODE>(Ap, Bt, sb, m0, n0, tid, (i + 2) % STAGES, (i + 2) * TK);
        CP_COMMIT();

        const float* As = smemf + slot * STAGE_F;
        const float* Bs = As + 4096;

#pragma unroll
        for (int ks = 0; ks < 4; ks++) {
            const int c0 = ((ks * 8) + tig) ^ xr;
            const int c4 = c0 ^ 4;

            uint32_t a[2][4];
#pragma unroll
            for (int mt = 0; mt < 2; mt++) {
                const int r0 = wm + mt * 16 + gid;
                const int r1 = r0 + 8;
                a[mt][0] = f2tf32(As[r0 * 32 + c0]);
                a[mt][1] = f2tf32(As[r1 * 32 + c0]);
                a[mt][2] = f2tf32(As[r0 * 32 + c4]);
                a[mt][3] = f2tf32(As[r1 * 32 + c4]);
            }
#pragma unroll
            for (int nt = 0; nt < 8; nt++) {
                const int n = wn + nt * 8 + gid;
                const uint32_t b0 = f2tf32(Bs[n * 32 + c0]);
                const uint32_t b1 = f2tf32(Bs[n * 32 + c4]);
                mma_tf32(acc[0][nt], a[0][0], a[0][1], a[0][2], a[0][3], b0, b1);
                mma_tf32(acc[1][nt], a[1][0], a[1][1], a[1][2], a[1][3], b0, b1);
            }
        }
        slot = (slot + 1) % STAGES;
    }

#pragma unroll
    for (int mt = 0; mt < 2; mt++) {
#pragma unroll
        for (int half = 0; half < 2; half++) {
            const int row = m0 + wm + mt * 16 + gid + half * 8;
#pragma unroll
            for (int nt = 0; nt < 8; nt++) {
                const int col = n0 + wn + nt * 8 + tig * 2;
                float v0 = acc[mt][nt][half * 2 + 0] + bias[col];
                float v1 = acc[mt][nt][half * 2 + 1] + bias[col + 1];

                if (MODE == 1) {
                    *(float2*)&Cout[(size_t)row * CDIM + col] = make_float2(v0, v1);
                } else {
                    const int sec = col >> 10;
                    const int n2  = col & 1023;
                    const float* hb = (sec == 0) ? bQ : (sec == 1) ? bK : bV;
                    v0 += hb[n2];
                    v1 += hb[n2 + 1];
                    const int h  = n2 >> 6, dd = n2 & 63;
                    const int b_ = row >> 11, t = row & (TLEN - 1);
                    float* base = (sec == 0) ? g_q : (sec == 1) ? g_k : g_v;
                    *(float2*)&base[(((size_t)(b_ * NHEAD + h) * TLEN) + t) * HDIM + dd] =
                        make_float2(v0, v1);
                }
            }
        }
    }
}

// ---------------------------------------------------------------------------
// Flash attention v7 = R13 with:
//  (1) V pre-converted to tf32 bits at tile load (stored as floats, same size)
//  (2) P stored tf32-rounded at exp time (row-sum uses exact p)
//  (3) S-loop: split A (Q, hi/lo -> 2 mma) + plain-tf32 B (K, 1 cvt)
// Error model: K rounding adds ~2.4e-4 abs in logits -> rel_err ~6.0e-4 total.
// SMEM footprint unchanged (70656 B) -> 3 CTA/SM preserved.
// ---------------------------------------------------------------------------
#define FL_SMEM (17664 * 4)   // Qs 4352 + Ks 4352 + Vs 4608 + Ps 4352 floats

__global__ __launch_bounds__(128, 2)
void flash_mma()
{
    extern __shared__ float sm[];
    float* Qs = sm;            // [64][68] raw (pre-scaled)
    float* Ks = sm + 4352;     // [64][68] raw
    float* Vs = sm + 8704;     // [64][72] tf32-rounded bits (Vs[key][dim])
    float* Ps = sm + 13312;    // [64][68] tf32-rounded bits

    const int tid  = threadIdx.x;
    const int lane = tid & 31;
    const int wid  = tid >> 5;
    const int gid  = lane >> 2;
    const int tig  = lane & 3;
    const int wr0  = wid * 16;

    const int qt = (int)gridDim.x - 1 - (int)blockIdx.x;   // heavy tiles first
    const int h  = blockIdx.y;
    const int b  = blockIdx.z;
    const int bh = b * NHEAD + h;
    const int q0 = qt * 64;

    // Load Q tile (pre-scaled by 1/sqrt(d))
    for (int idx = tid; idx < 64 * 16; idx += 128) {
        const int row = idx >> 4, c = (idx & 15) * 4;
        float4 v = *(const float4*)(g_q + ((size_t)bh * TLEN + q0 + row) * HDIM + c);
        *(float4*)(Qs + row * 68 + c) =
            make_float4(v.x * 0.125f, v.y * 0.125f, v.z * 0.125f, v.w * 0.125f);
    }

    float o[8][4];
#pragma unroll
    for (int nt = 0; nt < 8; nt++)
#pragma unroll
        for (int j = 0; j < 4; j++) o[nt][j] = 0.0f;
    float mrow[2] = {-1e30f, -1e30f};
    float lrow[2] = {0.0f, 0.0f};

    for (int kt = 0; kt <= qt; kt++) {
        __syncthreads();   // previous iteration done with Ks/Vs/Ps
        for (int idx = tid; idx < 64 * 16; idx += 128) {
            const int row = idx >> 4, c = (idx & 15) * 4;
            const size_t src = ((size_t)bh * TLEN + kt * 64 + row) * HDIM + c;
            *(float4*)(Ks + row * 68 + c) = *(const float4*)(g_k + src);
            float4 vv = *(const float4*)(g_v + src);
            float* vd = Vs + row * 72 + c;
            vd[0] = __uint_as_float(f2tf32(vv.x));
            vd[1] = __uint_as_float(f2tf32(vv.y));
            vd[2] = __uint_as_float(f2tf32(vv.z));
            vd[3] = __uint_as_float(f2tf32(vv.w));
        }
        __syncthreads();

        // ---- S = Q K^T (split A, plain-tf32 B: 2 mma) ----
        float s[8][4];
#pragma unroll
        for (int nt = 0; nt < 8; nt++)
#pragma unroll
            for (int j = 0; j < 4; j++) s[nt][j] = 0.0f;

#pragma unroll 2
        for (int ks = 0; ks < 8; ks++) {
            const int kc = ks * 8 + tig;
            float af[4];
            af[0] = Qs[(wr0 + gid) * 68 + kc];
            af[1] = Qs[(wr0 + gid + 8) * 68 + kc];
            af[2] = Qs[(wr0 + gid) * 68 + kc + 4];
            af[3] = Qs[(wr0 + gid + 8) * 68 + kc + 4];
            uint32_t ah[4], al[4];
#pragma unroll
            for (int j = 0; j < 4; j++) {
                ah[j] = f2tf32(af[j]);
                al[j] = f2tf32(af[j] - __uint_as_float(ah[j]));
            }
#pragma unroll
            for (int nt = 0; nt < 8; nt++) {
                const uint32_t b0 = f2tf32(Ks[(nt * 8 + gid) * 68 + kc]);
                const uint32_t b1 = f2tf32(Ks[(nt * 8 + gid) * 68 + kc + 4]);
                mma_tf32(s[nt], ah[0], ah[1], ah[2], ah[3], b0, b1);
                mma_tf32(s[nt], al[0], al[1], al[2], al[3], b0, b1);
            }
        }

        // Causal mask (only the diagonal tile)
        if (kt == qt) {
#pragma unroll
            for (int nt = 0; nt < 8; nt++) {
#pragma unroll
                for (int j = 0; j < 4; j++) {
                    const int col = nt * 8 + 2 * tig + (j & 1);
                    const int row = wr0 + gid + (j >> 1) * 8;
                    if (col > row) s[nt][j] = -1e30f;
                }
            }
        }

        // Row max over tile (quad reduction)
        float tmax[2] = {-1e30f, -1e30f};
#pragma unroll
        for (int nt = 0; nt < 8; nt++) {
            tmax[0] = fmaxf(tmax[0], fmaxf(s[nt][0], s[nt][1]));
            tmax[1] = fmaxf(tmax[1], fmaxf(s[nt][2], s[nt][3]));
        }
#pragma unroll
        for (int d = 1; d <= 2; d <<= 1) {
            tmax[0] = fmaxf(tmax[0], __shfl_xor_sync(0xFFFFFFFFu, tmax[0], d));
            tmax[1] = fmaxf(tmax[1], __shfl_xor_sync(0xFFFFFFFFu, tmax[1], d));
        }
        const float mnew0 = fmaxf(mrow[0], tmax[0]);
        const float mnew1 = fmaxf(mrow[1], tmax[1]);
        const float corr0 = __expf(mrow[0] - mnew0);
        const float corr1 = __expf(mrow[1] - mnew1);

        // p = exp(s - m); sums use exact p; store tf32-rounded p for PV
        float ps[2] = {0.0f, 0.0f};
#pragma unroll
        for (int nt = 0; nt < 8; nt++) {
            const float p0 = __expf(s[nt][0] - mnew0);
            const float p1 = __expf(s[nt][1] - mnew0);
            const float p2 = __expf(s[nt][2] - mnew1);
            const float p3 = __expf(s[nt][3] - mnew1);
            ps[0] += p0 + p1;
            ps[1] += p2 + p3;
            *(float2*)(Ps + (wr0 + gid) * 68 + nt * 8 + 2 * tig) =
                make_float2(__uint_as_float(f2tf32(p0)), __uint_as_float(f2tf32(p1)));
            *(float2*)(Ps + (wr0 + gid + 8) * 68 + nt * 8 + 2 * tig) =
                make_float2(__uint_as_float(f2tf32(p2)), __uint_as_float(f2tf32(p3)));
        }
#pragma unroll
        for (int d = 1; d <= 2; d <<= 1) {
            ps[0] += __shfl_xor_sync(0xFFFFFFFFu, ps[0], d);
            ps[1] += __shfl_xor_sync(0xFFFFFFFFu, ps[1], d);
        }
        lrow[0] = lrow[0] * corr0 + ps[0];
        lrow[1] = lrow[1] * corr1 + ps[1];
#pragma unroll
        for (int nt = 0; nt < 8; nt++) {
            o[nt][0] *= corr0; o[nt][1] *= corr0;
            o[nt][2] *= corr1; o[nt][3] *= corr1;
        }
        mrow[0] = mnew0;
        mrow[1] = mnew1;
        __syncwarp();   // P rows of this warp visible to the whole warp

        // ---- O += P V (all operands pre-rounded: pure LDS + mma) ----
#pragma unroll 2
        for (int ks = 0; ks < 8; ks++) {
            const int kc = ks * 8 + tig;
            const uint32_t A0 = __float_as_uint(Ps[(wr0 + gid) * 68 + kc]);
            const uint32_t A1 = __float_as_uint(Ps[(wr0 + gid + 8) * 68 + kc]);
            const uint32_t A2 = __float_as_uint(Ps[(wr0 + gid) * 68 + kc + 4]);
            const uint32_t A3 = __float_as_uint(Ps[(wr0 + gid + 8) * 68 + kc + 4]);
#pragma unroll
            for (int nt = 0; nt < 8; nt++) {
                const uint32_t B0 = __float_as_uint(Vs[kc * 72 + nt * 8 + gid]);
                const uint32_t B1 = __float_as_uint(Vs[(kc + 4) * 72 + nt * 8 + gid]);
                mma_tf32(o[nt], A0, A1, A2, A3, B0, B1);
            }
        }
    }

    // Epilogue: divide by l, write to g_att [b,t, h*64+d]
    const float inv0 = 1.0f / lrow[0];
    const float inv1 = 1.0f / lrow[1];
    const size_t r0 = (size_t)b * TLEN + q0 + wr0 + gid;
#pragma unroll
    for (int nt = 0; nt < 8; nt++) {
        const int col = h * HDIM + nt * 8 + 2 * tig;
        *(float2*)(g_att + r0 * CDIM + col) =
            make_float2(o[nt][0] * inv0, o[nt][1] * inv0);
        *(float2*)(g_att + (r0 + 8) * CDIM + col) =
            make_float2(o[nt][2] * inv1, o[nt][3] * inv1);
    }
}

// ---------------------------------------------------------------------------
// kernel_launch
// Inputs: 0:x 1:W_attn 2:b_attn 3:W_proj 4:b_proj 5:bQ 6:bK 7:bV
// ---------------------------------------------------------------------------
extern "C" void kernel_launch(void* const* d_in, const int* in_sizes, int n_in,
                              void* d_out, int out_size)
{
    const float* x      = (const float*)d_in[0];
    const float* W_attn = (const float*)d_in[1];
    const float* b_attn = (const float*)d_in[2];
    const float* W_proj = (const float*)d_in[3];
    const float* b_proj = (const float*)d_in[4];
    const float* bQ     = (const float*)d_in[5];
    const float* bK     = (const float*)d_in[6];
    const float* bV     = (const float*)d_in[7];
    float* out = (float*)d_out;

    cudaFuncSetAttribute(tc_gemm<0>, cudaFuncAttributeMaxDynamicSharedMemorySize, SMEM_GEMM);
    cudaFuncSetAttribute(tc_gemm<1>, cudaFuncAttributeMaxDynamicSharedMemorySize, SMEM_GEMM);
    cudaFuncSetAttribute(flash_mma, cudaFuncAttributeMaxDynamicSharedMemorySize, FL_SMEM);

    // 0) Transpose weights into K-major form
    {
        dim3 tb(32, 8);
        transpose_k<<<dim3(3 * CDIM / 32, CDIM / 32), tb>>>(W_attn, 0, CDIM, 3 * CDIM);
        transpose_k<<<dim3(CDIM / 32, CDIM / 32), tb>>>(W_proj, WT_PROJ_OFF, CDIM, CDIM);
    }

    // 1) QKV GEMM (tf32 mma.sync) + bias + head scatter
    {
        dim3 grid(3 * CDIM / 128, MTOT / 128);   // (24, 64)
        tc_gemm<0><<<grid, 256, SMEM_GEMM>>>(x, 0, b_attn, bQ, bK, bV, nullptr);
    }

    // 2) Causal flash attention (split-A/plain-B S, pre-rounded PV)
    {
        dim3 grid(TLEN / 64, NHEAD, BSZ);        // (32, 16, 4)
        flash_mma<<<grid, 128, FL_SMEM>>>();
    }

    // 3) Projection GEMM (tf32 mma.sync) + b_proj
    {
        dim3 grid(CDIM / 128, MTOT / 128);       // (8, 64)
        tc_gemm<1><<<grid, 256, SMEM_GEMM>>>(nullptr, WT_PROJ_OFF, b_proj,
                                             nullptr, nullptr, nullptr, out);
    }
}

// round 15
// speedup vs baseline: 1.9768x; 1.0899x over previous
#include <cuda_runtime.h>
#include <cstdint>
#include <math.h>

// Problem constants
#define BSZ   4
#define TLEN  2048
#define CDIM  1024
#define NHEAD 16
#define HDIM  64
#define MTOT  (BSZ * TLEN)          // 8192

// ---------------------------------------------------------------------------
// Scratch (device globals — no allocation allowed)
// ---------------------------------------------------------------------------
__device__ float g_q[BSZ * NHEAD * TLEN * HDIM];   // [b,h,t,d] raw
__device__ float g_k[BSZ * NHEAD * TLEN * HDIM];   // tf32-rounded
__device__ float g_v[BSZ * NHEAD * TLEN * HDIM];   // tf32-rounded
__device__ float g_att[BSZ * TLEN * CDIM];         // [b,t,c] tf32-rounded
__device__ float g_wT[4 * CDIM * CDIM];            // W^T, tf32-rounded

#define WT_PROJ_OFF (3 * CDIM * CDIM)

// ---------------------------------------------------------------------------
// Portable PTX helpers (sm_80+ only; harness targets plain sm_100)
// ---------------------------------------------------------------------------
__device__ __forceinline__ uint32_t smem_u32(const void* p) {
    uint32_t a;
    asm("{ .reg .u64 t; cvta.to.shared.u64 t, %1; cvt.u32.u64 %0, t; }" : "=r"(a) : "l"(p));
    return a;
}

#define CP_ASYNC16(dst, src) \
    asm volatile("cp.async.cg.shared.global [%0], [%1], 16;" :: "r"(dst), "l"(src))
#define CP_COMMIT() asm volatile("cp.async.commit_group;")
#define CP_WAIT(n)  asm volatile("cp.async.wait_group %0;" :: "n"(n))

__device__ __forceinline__ uint32_t swz(uint32_t off) { return off ^ ((off >> 3) & 0x70); }

__device__ __forceinline__ uint32_t f2tf32(float f) {
    uint32_t r;
    asm("cvt.rna.tf32.f32 %0, %1;" : "=r"(r) : "f"(f));
    return r;
}
__device__ __forceinline__ float rnd_tf32(float f) { return __uint_as_float(f2tf32(f)); }

// m16n8k8 tf32 mma, fp32 accumulate (sm_80+)
__device__ __forceinline__ void mma_tf32(float c[4],
                                         uint32_t a0, uint32_t a1, uint32_t a2, uint32_t a3,
                                         uint32_t b0, uint32_t b1) {
    asm volatile(
        "mma.sync.aligned.m16n8k8.row.col.f32.tf32.tf32.f32 "
        "{%0,%1,%2,%3}, {%4,%5,%6,%7}, {%8,%9}, {%0,%1,%2,%3};"
        : "+f"(c[0]), "+f"(c[1]), "+f"(c[2]), "+f"(c[3])
        : "r"(a0), "r"(a1), "r"(a2), "r"(a3), "r"(b0), "r"(b1));
}

// ---------------------------------------------------------------------------
// Weight transpose: out[c][r] = tf32(in[r][c])  (pre-rounded for the GEMMs)
// ---------------------------------------------------------------------------
__global__ __launch_bounds__(256)
void transpose_k(const float* __restrict__ in, int dst_off, int R, int C)
{
    __shared__ float t[32][33];
    const int c0 = blockIdx.x * 32, r0 = blockIdx.y * 32;
    const int tx = threadIdx.x, ty = threadIdx.y;
#pragma unroll
    for (int i = ty; i < 32; i += 8)
        t[i][tx] = in[(r0 + i) * C + c0 + tx];
    __syncthreads();
#pragma unroll
    for (int i = ty; i < 32; i += 8)
        g_wT[dst_off + (c0 + i) * R + r0 + tx] = rnd_tf32(t[tx][i]);
}

// ---------------------------------------------------------------------------
// tf32 mma.sync GEMM. B (weights) arrive pre-rounded -> plain bit loads.
// MODE 0: A = x (raw -> cvt per use); epilogue rounds K/V sections on store.
// MODE 1: A = g_att (pre-rounded by flash epilogue -> bit loads).
// ---------------------------------------------------------------------------
#define TK          32
#define STAGES      3
#define STAGE_BYTES 32768
#define STAGE_F     8192
#define SMEM_GEMM   (STAGES * STAGE_BYTES)

template <int MODE>
__device__ __forceinline__ void load_stage(const float* Ap, const float* Bt,
                                           uint32_t sb, int m0, int n0, int tid,
                                           int s, int k0)
{
    const uint32_t base = sb + s * STAGE_BYTES;
#pragma unroll
    for (int j = 0; j < 4; j++) {
        const int idx = tid + j * 256;
        const int r = idx >> 3, c = idx & 7;
        CP_ASYNC16(base + swz(r * 128 + c * 16), Ap + (m0 + r) * CDIM + k0 + c * 4);
    }
#pragma unroll
    for (int j = 0; j < 4; j++) {
        const int idx = tid + j * 256;
        const int r = idx >> 3, c = idx & 7;
        CP_ASYNC16(base + 16384 + swz(r * 128 + c * 16), Bt + (n0 + r) * CDIM + k0 + c * 4);
    }
}

template <int MODE>
__global__ __launch_bounds__(256, 2)
void tc_gemm(const float* __restrict__ A,
             int bt_off,
             const float* __restrict__ bias,
             const float* __restrict__ bQ,
             const float* __restrict__ bK,
             const float* __restrict__ bV,
             float* __restrict__ Cout)
{
    extern __shared__ float smemf[];
    const uint32_t sb = smem_u32(smemf);
    const int tid  = threadIdx.x;
    const int lane = tid & 31;
    const int wid  = tid >> 5;
    const int gid  = lane >> 2;
    const int tig  = lane & 3;
    const int wm   = (wid & 3) * 32;
    const int wn   = (wid >> 2) * 64;

    const int m0 = blockIdx.y * 128;
    const int n0 = blockIdx.x * 128;

    const float* Ap = (MODE == 1) ? (const float*)g_att : A;
    const float* Bt = g_wT + bt_off;

    float acc[2][8][4];
#pragma unroll
    for (int mt = 0; mt < 2; mt++)
#pragma unroll
        for (int nt = 0; nt < 8; nt++)
#pragma unroll
            for (int j = 0; j < 4; j++) acc[mt][nt][j] = 0.0f;

    load_stage<MODE>(Ap, Bt, sb, m0, n0, tid, 0, 0);
    CP_COMMIT();
    load_stage<MODE>(Ap, Bt, sb, m0, n0, tid, 1, TK);
    CP_COMMIT();

    const int NIT = CDIM / TK;
    const int xr  = gid << 2;

    int slot = 0;
    for (int i = 0; i < NIT; i++) {
        CP_WAIT(1);
        __syncthreads();

        if (i + 2 < NIT)
            load_stage<MODE>(Ap, Bt, sb, m0, n0, tid, (i + 2) % STAGES, (i + 2) * TK);
        CP_COMMIT();

        const float* As = smemf + slot * STAGE_F;
        const float* Bs = As + 4096;

#pragma unroll
        for (int ks = 0; ks < 4; ks++) {
            const int c0 = ((ks * 8) + tig) ^ xr;
            const int c4 = c0 ^ 4;

            uint32_t a[2][4];
#pragma unroll
            for (int mt = 0; mt < 2; mt++) {
                const int r0 = wm + mt * 16 + gid;
                const int r1 = r0 + 8;
                if (MODE == 0) {
                    a[mt][0] = f2tf32(As[r0 * 32 + c0]);
                    a[mt][1] = f2tf32(As[r1 * 32 + c0]);
                    a[mt][2] = f2tf32(As[r0 * 32 + c4]);
                    a[mt][3] = f2tf32(As[r1 * 32 + c4]);
                } else {
                    a[mt][0] = __float_as_uint(As[r0 * 32 + c0]);
                    a[mt][1] = __float_as_uint(As[r1 * 32 + c0]);
                    a[mt][2] = __float_as_uint(As[r0 * 32 + c4]);
                    a[mt][3] = __float_as_uint(As[r1 * 32 + c4]);
                }
            }
#pragma unroll
            for (int nt = 0; nt < 8; nt++) {
                const int n = wn + nt * 8 + gid;
                const uint32_t b0 = __float_as_uint(Bs[n * 32 + c0]);
                const uint32_t b1 = __float_as_uint(Bs[n * 32 + c4]);
                mma_tf32(acc[0][nt], a[0][0], a[0][1], a[0][2], a[0][3], b0, b1);
                mma_tf32(acc[1][nt], a[1][0], a[1][1], a[1][2], a[1][3], b0, b1);
            }
        }
        slot = (slot + 1) % STAGES;
    }

#pragma unroll
    for (int mt = 0; mt < 2; mt++) {
#pragma unroll
        for (int half = 0; half < 2; half++) {
            const int row = m0 + wm + mt * 16 + gid + half * 8;
#pragma unroll
            for (int nt = 0; nt < 8; nt++) {
                const int col = n0 + wn + nt * 8 + tig * 2;
                float v0 = acc[mt][nt][half * 2 + 0] + bias[col];
                float v1 = acc[mt][nt][half * 2 + 1] + bias[col + 1];

                if (MODE == 1) {
                    *(float2*)&Cout[(size_t)row * CDIM + col] = make_float2(v0, v1);
                } else {
                    const int sec = col >> 10;
                    const int n2  = col & 1023;
                    const float* hb = (sec == 0) ? bQ : (sec == 1) ? bK : bV;
                    v0 += hb[n2];
                    v1 += hb[n2 + 1];
                    if (sec != 0) {           // K/V consumed plain-tf32: pre-round
                        v0 = rnd_tf32(v0);
                        v1 = rnd_tf32(v1);
                    }
                    const int h  = n2 >> 6, dd = n2 & 63;
                    const int b_ = row >> 11, t = row & (TLEN - 1);
                    float* base = (sec == 0) ? g_q : (sec == 1) ? g_k : g_v;
                    *(float2*)&base[(((size_t)(b_ * NHEAD + h) * TLEN) + t) * HDIM + dd] =
                        make_float2(v0, v1);
                }
            }
        }
    }
}

// ---------------------------------------------------------------------------
// Flash attention v8 = R14 with K/V arriving pre-rounded from the QKV GEMM:
// tile loads are pure copies; S-loop B and PV operands are bit loads.
// Q stays raw (split-A). Epilogue rounds g_att for the proj GEMM's A side.
// SMEM footprint unchanged (70656 B) -> 3 CTA/SM preserved.
// ---------------------------------------------------------------------------
#define FL_SMEM (17664 * 4)   // Qs 4352 + Ks 4352 + Vs 4608 + Ps 4352 floats

__global__ __launch_bounds__(128, 2)
void flash_mma()
{
    extern __shared__ float sm[];
    float* Qs = sm;            // [64][68] raw (pre-scaled)
    float* Ks = sm + 4352;     // [64][68] tf32 bits
    float* Vs = sm + 8704;     // [64][72] tf32 bits (Vs[key][dim])
    float* Ps = sm + 13312;    // [64][68] tf32 bits

    const int tid  = threadIdx.x;
    const int lane = tid & 31;
    const int wid  = tid >> 5;
    const int gid  = lane >> 2;
    const int tig  = lane & 3;
    const int wr0  = wid * 16;

    const int qt = (int)gridDim.x - 1 - (int)blockIdx.x;   // heavy tiles first
    const int h  = blockIdx.y;
    const int b  = blockIdx.z;
    const int bh = b * NHEAD + h;
    const int q0 = qt * 64;

    // Load Q tile (pre-scaled by 1/sqrt(d))
    for (int idx = tid; idx < 64 * 16; idx += 128) {
        const int row = idx >> 4, c = (idx & 15) * 4;
        float4 v = *(const float4*)(g_q + ((size_t)bh * TLEN + q0 + row) * HDIM + c);
        *(float4*)(Qs + row * 68 + c) =
            make_float4(v.x * 0.125f, v.y * 0.125f, v.z * 0.125f, v.w * 0.125f);
    }

    float o[8][4];
#pragma unroll
    for (int nt = 0; nt < 8; nt++)
#pragma unroll
        for (int j = 0; j < 4; j++) o[nt][j] = 0.0f;
    float mrow[2] = {-1e30f, -1e30f};
    float lrow[2] = {0.0f, 0.0f};

    for (int kt = 0; kt <= qt; kt++) {
        __syncthreads();   // previous iteration done with Ks/Vs/Ps
        for (int idx = tid; idx < 64 * 16; idx += 128) {
            const int row = idx >> 4, c = (idx & 15) * 4;
            const size_t src = ((size_t)bh * TLEN + kt * 64 + row) * HDIM + c;
            *(float4*)(Ks + row * 68 + c) = *(const float4*)(g_k + src);
            *(float4*)(Vs + row * 72 + c) = *(const float4*)(g_v + src);
        }
        __syncthreads();

        // ---- S = Q K^T (split A, pre-rounded B: 2 mma, zero B-side ALU) ----
        float s[8][4];
#pragma unroll
        for (int nt = 0; nt < 8; nt++)
#pragma unroll
            for (int j = 0; j < 4; j++) s[nt][j] = 0.0f;

#pragma unroll 2
        for (int ks = 0; ks < 8; ks++) {
            const int kc = ks * 8 + tig;
            float af[4];
            af[0] = Qs[(wr0 + gid) * 68 + kc];
            af[1] = Qs[(wr0 + gid + 8) * 68 + kc];
            af[2] = Qs[(wr0 + gid) * 68 + kc + 4];
            af[3] = Qs[(wr0 + gid + 8) * 68 + kc + 4];
            uint32_t ah[4], al[4];
#pragma unroll
            for (int j = 0; j < 4; j++) {
                ah[j] = f2tf32(af[j]);
                al[j] = f2tf32(af[j] - __uint_as_float(ah[j]));
            }
#pragma unroll
            for (int nt = 0; nt < 8; nt++) {
                const uint32_t b0 = __float_as_uint(Ks[(nt * 8 + gid) * 68 + kc]);
                const uint32_t b1 = __float_as_uint(Ks[(nt * 8 + gid) * 68 + kc + 4]);
                mma_tf32(s[nt], ah[0], ah[1], ah[2], ah[3], b0, b1);
                mma_tf32(s[nt], al[0], al[1], al[2], al[3], b0, b1);
            }
        }

        // Causal mask (only the diagonal tile)
        if (kt == qt) {
#pragma unroll
            for (int nt = 0; nt < 8; nt++) {
#pragma unroll
                for (int j = 0; j < 4; j++) {
                    const int col = nt * 8 + 2 * tig + (j & 1);
                    const int row = wr0 + gid + (j >> 1) * 8;
                    if (col > row) s[nt][j] = -1e30f;
                }
            }
        }

        // Row max over tile (quad reduction)
        float tmax[2] = {-1e30f, -1e30f};
#pragma unroll
        for (int nt = 0; nt < 8; nt++) {
            tmax[0] = fmaxf(tmax[0], fmaxf(s[nt][0], s[nt][1]));
            tmax[1] = fmaxf(tmax[1], fmaxf(s[nt][2], s[nt][3]));
        }
#pragma unroll
        for (int d = 1; d <= 2; d <<= 1) {
            tmax[0] = fmaxf(tmax[0], __shfl_xor_sync(0xFFFFFFFFu, tmax[0], d));
            tmax[1] = fmaxf(tmax[1], __shfl_xor_sync(0xFFFFFFFFu, tmax[1], d));
        }
        const float mnew0 = fmaxf(mrow[0], tmax[0]);
        const float mnew1 = fmaxf(mrow[1], tmax[1]);
        const float corr0 = __expf(mrow[0] - mnew0);
        const float corr1 = __expf(mrow[1] - mnew1);

        // p = exp(s - m); sums use exact p; store tf32-rounded p for PV
        float ps[2] = {0.0f, 0.0f};
#pragma unroll
        for (int nt = 0; nt < 8; nt++) {
            const float p0 = __expf(s[nt][0] - mnew0);
            const float p1 = __expf(s[nt][1] - mnew0);
            const float p2 = __expf(s[nt][2] - mnew1);
            const float p3 = __expf(s[nt][3] - mnew1);
            ps[0] += p0 + p1;
            ps[1] += p2 + p3;
            *(float2*)(Ps + (wr0 + gid) * 68 + nt * 8 + 2 * tig) =
                make_float2(rnd_tf32(p0), rnd_tf32(p1));
            *(float2*)(Ps + (wr0 + gid + 8) * 68 + nt * 8 + 2 * tig) =
                make_float2(rnd_tf32(p2), rnd_tf32(p3));
        }
#pragma unroll
        for (int d = 1; d <= 2; d <<= 1) {
            ps[0] += __shfl_xor_sync(0xFFFFFFFFu, ps[0], d);
            ps[1] += __shfl_xor_sync(0xFFFFFFFFu, ps[1], d);
        }
        lrow[0] = lrow[0] * corr0 + ps[0];
        lrow[1] = lrow[1] * corr1 + ps[1];
#pragma unroll
        for (int nt = 0; nt < 8; nt++) {
            o[nt][0] *= corr0; o[nt][1] *= corr0;
            o[nt][2] *= corr1; o[nt][3] *= corr1;
        }
        mrow[0] = mnew0;
        mrow[1] = mnew1;
        __syncwarp();   // P rows of this warp visible to the whole warp

        // ---- O += P V (all operands pre-rounded: pure LDS + mma) ----
#pragma unroll 2
        for (int ks = 0; ks < 8; ks++) {
            const int kc = ks * 8 + tig;
            const uint32_t A0 = __float_as_uint(Ps[(wr0 + gid) * 68 + kc]);
            const uint32_t A1 = __float_as_uint(Ps[(wr0 + gid + 8) * 68 + kc]);
            const uint32_t A2 = __float_as_uint(Ps[(wr0 + gid) * 68 + kc + 4]);
            const uint32_t A3 = __float_as_uint(Ps[(wr0 + gid + 8) * 68 + kc + 4]);
#pragma unroll
            for (int nt = 0; nt < 8; nt++) {
                const uint32_t B0 = __float_as_uint(Vs[kc * 72 + nt * 8 + gid]);
                const uint32_t B1 = __float_as_uint(Vs[(kc + 4) * 72 + nt * 8 + gid]);
                mma_tf32(o[nt], A0, A1, A2, A3, B0, B1);
            }
        }
    }

    // Epilogue: divide by l; store tf32-rounded (proj GEMM reads A as bits)
    const float inv0 = 1.0f / lrow[0];
    const float inv1 = 1.0f / lrow[1];
    const size_t r0 = (size_t)b * TLEN + q0 + wr0 + gid;
#pragma unroll
    for (int nt = 0; nt < 8; nt++) {
        const int col = h * HDIM + nt * 8 + 2 * tig;
        *(float2*)(g_att + r0 * CDIM + col) =
            make_float2(rnd_tf32(o[nt][0] * inv0), rnd_tf32(o[nt][1] * inv0));
        *(float2*)(g_att + (r0 + 8) * CDIM + col) =
            make_float2(rnd_tf32(o[nt][2] * inv1), rnd_tf32(o[nt][3] * inv1));
    }
}

// ---------------------------------------------------------------------------
// kernel_launch
// Inputs: 0:x 1:W_attn 2:b_attn 3:W_proj 4:b_proj 5:bQ 6:bK 7:bV
// ---------------------------------------------------------------------------
extern "C" void kernel_launch(void* const* d_in, const int* in_sizes, int n_in,
                              void* d_out, int out_size)
{
    const float* x      = (const float*)d_in[0];
    const float* W_attn = (const float*)d_in[1];
    const float* b_attn = (const float*)d_in[2];
    const float* W_proj = (const float*)d_in[3];
    const float* b_proj = (const float*)d_in[4];
    const float* bQ     = (const float*)d_in[5];
    const float* bK     = (const float*)d_in[6];
    const float* bV     = (const float*)d_in[7];
    float* out = (float*)d_out;

    cudaFuncSetAttribute(tc_gemm<0>, cudaFuncAttributeMaxDynamicSharedMemorySize, SMEM_GEMM);
    cudaFuncSetAttribute(tc_gemm<1>, cudaFuncAttributeMaxDynamicSharedMemorySize, SMEM_GEMM);
    cudaFuncSetAttribute(flash_mma, cudaFuncAttributeMaxDynamicSharedMemorySize, FL_SMEM);

    // 0) Transpose weights into K-major form (pre-rounded to tf32)
    {
        dim3 tb(32, 8);
        transpose_k<<<dim3(3 * CDIM / 32, CDIM / 32), tb>>>(W_attn, 0, CDIM, 3 * CDIM);
        transpose_k<<<dim3(CDIM / 32, CDIM / 32), tb>>>(W_proj, WT_PROJ_OFF, CDIM, CDIM);
    }

    // 1) QKV GEMM (tf32 mma.sync) + bias + head scatter (K/V pre-rounded)
    {
        dim3 grid(3 * CDIM / 128, MTOT / 128);   // (24, 64)
        tc_gemm<0><<<grid, 256, SMEM_GEMM>>>(x, 0, b_attn, bQ, bK, bV, nullptr);
    }

    // 2) Causal flash attention (split-A S, all plain operands pre-rounded)
    {
        dim3 grid(TLEN / 64, NHEAD, BSZ);        // (32, 16, 4)
        flash_mma<<<grid, 128, FL_SMEM>>>();
    }

    // 3) Projection GEMM (tf32 mma.sync) + b_proj
    {
        dim3 grid(CDIM / 128, MTOT / 128);       // (8, 64)
        tc_gemm<1><<<grid, 256, SMEM_GEMM>>>(nullptr, WT_PROJ_OFF, b_proj,
                                             nullptr, nullptr, nullptr, out);
    }
}